// round 3
// baseline (speedup 1.0000x reference)
#include <cuda_runtime.h>
#include <cuda_bf16.h>

#define BB 4
#define TT 5
#define NXX 512
#define NYY 512
#define HID 64
#define NFP 4
#define PLANE (NXX*NYY)          // 262144
#define NPB (TT*PLANE)           // 1310720 elements per batch
#define FIELD (BB*NPB)           // 5242880

// ---------------- scratch (static device globals; no allocation) -------------
__device__ float  g_xbuf[2][FIELD];             // ping-pong x_k  (~42 MB)
__device__ float  g_hid[BB*HID*PLANE];          // hidden activations (~268 MB)
__device__ double g_acc[BB][NFP+1][2];          // cost accumulators

// ---------------- cost row: mse + (dy_term + x^T Q x) ------------------------
// Q: 6.01 on diag, -1 for each adjacent pair along t / dim2 / dim3 (symmetric)
// => xtQx = 6.01*sum(x^2) - 2*sum_{adjacent pairs} x_i*x_j
__global__ void cost_kernel(const float* __restrict__ x,
                            const float* __restrict__ gt,
                            const float* __restrict__ yobs,
                            const int*   __restrict__ mask,
                            int row)
{
    int b = blockIdx.y;
    const float* xb  = x    + b*NPB;
    const float* gtb = gt   + b*NPB;
    const float* yb  = yobs + b*NPB;
    const int*   mb  = mask + b*NPB;

    double s_mse = 0.0, s_oi = 0.0;
    for (int i = blockIdx.x*blockDim.x + threadIdx.x; i < NPB;
         i += blockDim.x*gridDim.x) {
        int t  = i / PLANE;
        int r  = i - t*PLANE;
        int ix = r >> 9;        // dim2 index (0..511)
        int iy = r & 511;       // dim3 index (0..511)

        float xv = xb[i];
        float g  = gtb[i] - xv;
        s_mse += (double)(g*g);

        float m = (float)mb[i];
        float d = xv - yb[i];

        float nb = 0.0f;
        if (t  < TT-1)  nb += xb[i + PLANE];
        if (ix < NXX-1) nb += xb[i + NYY];
        if (iy < NYY-1) nb += xb[i + 1];

        float oi = 1000.0f*m*d*d + 6.01f*xv*xv - 2.0f*xv*nb;
        s_oi += (double)oi;
    }

    // warp + block reduce (double)
    #pragma unroll
    for (int off = 16; off; off >>= 1) {
        s_mse += __shfl_down_sync(0xffffffffu, s_mse, off);
        s_oi  += __shfl_down_sync(0xffffffffu, s_oi,  off);
    }
    __shared__ double red[2][8];
    int lane = threadIdx.x & 31, w = threadIdx.x >> 5;
    if (lane == 0) { red[0][w] = s_mse; red[1][w] = s_oi; }
    __syncthreads();
    if (threadIdx.x == 0) {
        double a = 0.0, c = 0.0;
        #pragma unroll
        for (int i2 = 0; i2 < 8; i2++) { a += red[0][i2]; c += red[1][i2]; }
        atomicAdd(&g_acc[b][row][0], a);
        atomicAdd(&g_acc[b][row][1], c);
    }
}

// ---------------- conv1: [B,5,H,W] -> relu(conv3x3 + b1) -> [B,64,H,W] -------
#define TX1 32
#define TY1 8
__global__ __launch_bounds__(256)
void conv1_kernel(const float* __restrict__ in,
                  const float* __restrict__ W1,   // [64,5,3,3]
                  const float* __restrict__ b1,   // [64]
                  float* __restrict__ out)        // [B,64,H,W]
{
    __shared__ float sw[45*64];                   // [tap(ic*9+k)][oc]
    __shared__ float sb[64];
    __shared__ float sin[TT][TY1+2][TX1+2];

    int b  = blockIdx.z;
    int x0 = blockIdx.x * TX1;
    int y0 = blockIdx.y * TY1;
    int tid = threadIdx.x;

    for (int i = tid; i < 45*64; i += 256) {
        int oc = i & 63, kt = i >> 6;
        sw[i] = W1[oc*45 + kt];
    }
    if (tid < 64) sb[tid] = b1[tid];

    for (int i = tid; i < TT*(TY1+2)*(TX1+2); i += 256) {
        int c  = i / ((TY1+2)*(TX1+2));
        int rr = i % ((TY1+2)*(TX1+2));
        int yy = rr / (TX1+2);
        int xx = rr % (TX1+2);
        int gy = y0 + yy - 1;
        int gx = x0 + xx - 1;
        float v = 0.0f;
        if (gy >= 0 && gy < NXX && gx >= 0 && gx < NYY)
            v = in[(b*TT + c)*PLANE + gy*NYY + gx];
        sin[c][yy][xx] = v;
    }
    __syncthreads();

    int tx = tid & 31;
    int ty = tid >> 5;

    float acc[64];
    #pragma unroll
    for (int oc = 0; oc < 64; oc++) acc[oc] = sb[oc];

    #pragma unroll 1
    for (int c = 0; c < TT; c++) {
        #pragma unroll
        for (int ky = 0; ky < 3; ky++) {
            #pragma unroll
            for (int kx = 0; kx < 3; kx++) {
                float v = sin[c][ty+ky][tx+kx];
                const float4* w4 = (const float4*)&sw[(c*9 + ky*3 + kx) << 6];
                #pragma unroll
                for (int o = 0; o < 16; o++) {
                    float4 w = w4[o];
                    acc[4*o+0] += w.x * v;
                    acc[4*o+1] += w.y * v;
                    acc[4*o+2] += w.z * v;
                    acc[4*o+3] += w.w * v;
                }
            }
        }
    }

    int gy = y0 + ty, gx = x0 + tx;
    float* ob = out + b*HID*PLANE + gy*NYY + gx;
    #pragma unroll
    for (int oc = 0; oc < 64; oc++)
        ob[oc*PLANE] = fmaxf(acc[oc], 0.0f);
}

// ---------------- conv2: [B,64,H,W] -> conv3x3 + b2 -> [B,5,H,W] (+mask fuse)
#define TX2 32
#define TY2 4
#define ICC 16
__global__ __launch_bounds__(128)
void conv2_kernel(const float* __restrict__ hid,
                  const float* __restrict__ W2,    // [5,64,3,3]
                  const float* __restrict__ b2,    // [5]
                  const float* __restrict__ yobs,
                  const int*   __restrict__ mask,
                  float* __restrict__ out,
                  int apply_mask)
{
    __shared__ float sw[576*8];                    // [tap(ic*9+k)][oc pad 8]
    __shared__ float sin[ICC][TY2+2][TX2+2];

    int b  = blockIdx.z;
    int x0 = blockIdx.x * TX2;
    int y0 = blockIdx.y * TY2;
    int tid = threadIdx.x;

    for (int i = tid; i < 576*5; i += 128) {
        int kt = i / 5, oc = i - kt*5;
        sw[kt*8 + oc] = W2[oc*576 + kt];
    }

    float acc[5];
    #pragma unroll
    for (int o = 0; o < 5; o++) acc[o] = b2[o];

    int tx = tid & 31;
    int ty = tid >> 5;

    for (int c0 = 0; c0 < HID; c0 += ICC) {
        __syncthreads();
        for (int i = tid; i < ICC*(TY2+2)*(TX2+2); i += 128) {
            int c  = i / ((TY2+2)*(TX2+2));
            int rr = i % ((TY2+2)*(TX2+2));
            int yy = rr / (TX2+2);
            int xx = rr % (TX2+2);
            int gy = y0 + yy - 1;
            int gx = x0 + xx - 1;
            float v = 0.0f;
            if (gy >= 0 && gy < NXX && gx >= 0 && gx < NYY)
                v = hid[(b*HID + c0 + c)*PLANE + gy*NYY + gx];
            sin[c][yy][xx] = v;
        }
        __syncthreads();

        #pragma unroll 1
        for (int c = 0; c < ICC; c++) {
            #pragma unroll
            for (int ky = 0; ky < 3; ky++) {
                #pragma unroll
                for (int kx = 0; kx < 3; kx++) {
                    float v = sin[c][ty+ky][tx+kx];
                    const float* w = &sw[((c0 + c)*9 + ky*3 + kx)*8];
                    float4 w4 = *(const float4*)w;
                    float  w5 = w[4];
                    acc[0] += w4.x * v;
                    acc[1] += w4.y * v;
                    acc[2] += w4.z * v;
                    acc[3] += w4.w * v;
                    acc[4] += w5   * v;
                }
            }
        }
    }

    int gy = y0 + ty, gx = x0 + tx;
    int base = b*NPB + gy*NYY + gx;
    #pragma unroll
    for (int o = 0; o < 5; o++) {
        int idx = base + o*PLANE;
        float v = acc[o];
        if (apply_mask) {
            float m = (float)mask[idx];
            v = v*(1.0f - m) + yobs[idx]*m;
        }
        out[idx] = v;
    }
}

// ---------------- finalize cmp_loss [B, NFP+1, 2] ----------------------------
__global__ void finalize_kernel(float* __restrict__ cmp)
{
    int i = threadIdx.x;
    if (i < BB*(NFP+1)*2) {
        int b = i / ((NFP+1)*2);
        int r = (i / 2) % (NFP+1);
        int c = i & 1;
        double v = g_acc[b][r][c];
        if (c == 0) v /= (double)NPB;       // mean for MSE
        cmp[i] = (float)v;
    }
}

// ---------------- launcher ---------------------------------------------------
extern "C" void kernel_launch(void* const* d_in, const int* in_sizes, int n_in,
                              void* d_out, int out_size)
{
    const float* gt   = (const float*)d_in[0];
    const float* x    = (const float*)d_in[1];
    const float* yobs = (const float*)d_in[2];
    const int*   mask = (const int*)  d_in[3];
    const float* W1   = (const float*)d_in[4];
    const float* b1   = (const float*)d_in[5];
    const float* W2   = (const float*)d_in[6];
    const float* b2   = (const float*)d_in[7];
    (void)in_sizes; (void)n_in;

    float* out     = (float*)d_out;
    float* out_x   = out;                                  // [B,5,512,512]
    float* out_cmp = out + (out_size - BB*(NFP+1)*2);      // [B,NFP+1,2]

    void *p0, *p1, *p2;
    cudaGetSymbolAddress(&p0, g_xbuf);
    cudaGetSymbolAddress(&p1, g_hid);
    cudaGetSymbolAddress(&p2, g_acc);
    float* xb0 = (float*)p0;
    float* xb1 = xb0 + FIELD;
    float* hid = (float*)p1;

    cudaMemsetAsync(p2, 0, sizeof(double)*BB*(NFP+1)*2);
    cudaMemcpyAsync(xb0, x, sizeof(float)*FIELD, cudaMemcpyDeviceToDevice);

    dim3 cgrid(640, BB);
    dim3 g1(NYY/TX1, NXX/TY1, BB);   // (16, 64, 4)
    dim3 g2(NYY/TX2, NXX/TY2, BB);   // (16, 128, 4)

    float* cur = xb0;
    float* nxt = xb1;
    for (int k = 0; k < NFP; k++) {
        cost_kernel<<<cgrid, 256>>>(cur, gt, yobs, mask, k);
        conv1_kernel<<<g1, 256>>>(cur, W1, b1, hid);
        conv2_kernel<<<g2, 128>>>(hid, W2, b2, yobs, mask, nxt, 1);
        float* tmp = cur; cur = nxt; nxt = tmp;
    }
    // final phi (no mask blend), straight into d_out
    conv1_kernel<<<g1, 256>>>(cur, W1, b1, hid);
    conv2_kernel<<<g2, 128>>>(hid, W2, b2, yobs, mask, out_x, 0);
    cost_kernel<<<cgrid, 256>>>(out_x, gt, yobs, mask, NFP);
    finalize_kernel<<<1, 64>>>(out_cmp);
}

// round 7
// speedup vs baseline: 1.1007x; 1.1007x over previous
#include <cuda_runtime.h>
#include <cuda_bf16.h>

#define BB 4
#define TT 5
#define NXX 512
#define NYY 512
#define HID 64
#define NFP 4
#define PLANE (NXX*NYY)          // 262144 = 2^18
#define NPB (TT*PLANE)           // 1310720 elements per batch
#define FIELD (BB*NPB)           // 5242880

typedef unsigned long long ull;

// packed fp32x2 FMA (Blackwell-only; ptxas never auto-fuses this)
#define FMA2(d, a, b, c) \
    asm("fma.rn.f32x2 %0, %1, %2, %3;" : "=l"(d) : "l"(a), "l"(b), "l"(c))
#define PACK2(out, lo, hi) \
    asm("mov.b64 %0, {%1, %2};" : "=l"(out) : "r"(lo), "r"(hi))
#define UNPACK2(lo, hi, in) \
    asm("mov.b64 {%0, %1}, %2;" : "=r"(lo), "=r"(hi) : "l"(in))

// ---------------- scratch (static device globals; no allocation) -------------
__device__ float  g_xbuf[2][FIELD];             // ping-pong x_k  (~42 MB)
__device__ float  g_hid[BB*HID*PLANE];          // hidden activations (~268 MB)
__device__ double g_acc[BB][NFP+1][2];          // cost accumulators

// ---------------- cost row: mse + (dy_term + x^T Q x) ------------------------
// Q: 6.01 diag, -1 per adjacent pair along t / dim2 / dim3 (symmetric)
// => xtQx = 6.01*sum(x^2) - 2*sum_{adjacent pairs} x_i*x_j
__global__ __launch_bounds__(256)
void cost_kernel(const float* __restrict__ x,
                 const float* __restrict__ gt,
                 const float* __restrict__ yobs,
                 const int*   __restrict__ mask,
                 int row)
{
    int b = blockIdx.y;
    const float* xb = x + b*NPB;
    int j = blockIdx.x*256 + threadIdx.x;     // float4 group index, exact grid

    float s_mse = 0.0f, s_oi = 0.0f;
    {
        int i  = j << 2;
        int t  = i >> 18;
        int ix = (i >> 9) & 511;
        int iy = i & 511;
        const float4 z4 = make_float4(0.f, 0.f, 0.f, 0.f);

        float4 xv = ((const float4*)xb)[j];
        float4 gv = ((const float4*)(gt   + b*NPB))[j];
        float4 yv = ((const float4*)(yobs + b*NPB))[j];
        int4   mv = ((const int4*)(mask + b*NPB))[j];
        float4 xd = (ix < NXX-1) ? ((const float4*)xb)[j + NYY/4]     : z4;
        float4 xt = (t  < TT-1)  ? ((const float4*)xb)[j + PLANE/4]   : z4;
        float nxt = (iy != NYY-4) ? xb[i + 4] : 0.0f;

        float xa[4] = {xv.x, xv.y, xv.z, xv.w};
        float ga[4] = {gv.x, gv.y, gv.z, gv.w};
        float ya[4] = {yv.x, yv.y, yv.z, yv.w};
        float ma[4] = {(float)mv.x, (float)mv.y, (float)mv.z, (float)mv.w};
        float da[4] = {xd.x, xd.y, xd.z, xd.w};
        float ta[4] = {xt.x, xt.y, xt.z, xt.w};
        float ra[4] = {xv.y, xv.z, xv.w, nxt};

        #pragma unroll
        for (int e = 0; e < 4; e++) {
            float g = ga[e] - xa[e];
            s_mse += g*g;
            float d  = xa[e] - ya[e];
            float nb = ra[e] + da[e] + ta[e];
            s_oi += 1000.0f*ma[e]*d*d + 6.01f*xa[e]*xa[e] - 2.0f*xa[e]*nb;
        }
    }

    double dm = (double)s_mse, doi = (double)s_oi;
    #pragma unroll
    for (int off = 16; off; off >>= 1) {
        dm  += __shfl_down_sync(0xffffffffu, dm,  off);
        doi += __shfl_down_sync(0xffffffffu, doi, off);
    }
    __shared__ double red[2][8];
    int lane = threadIdx.x & 31, w = threadIdx.x >> 5;
    if (lane == 0) { red[0][w] = dm; red[1][w] = doi; }
    __syncthreads();
    if (threadIdx.x == 0) {
        double a = 0.0, c = 0.0;
        #pragma unroll
        for (int i2 = 0; i2 < 8; i2++) { a += red[0][i2]; c += red[1][i2]; }
        atomicAdd(&g_acc[b][row][0], a);
        atomicAdd(&g_acc[b][row][1], c);
    }
}

// ---------------- conv1: [B,5,H,W] -> relu(conv3x3 + b1) -> [B,64,H,W] -------
// FFMA2 over paired output channels: 32 packed accumulators per thread.
#define TX1 32
#define TY1 8
__global__ __launch_bounds__(256, 2)
void conv1_kernel(const float* __restrict__ in,
                  const float* __restrict__ W1,   // [64,5,3,3]
                  const float* __restrict__ b1,   // [64]
                  float* __restrict__ out)        // [B,64,H,W]
{
    __shared__ __align__(16) float sw[45*64];     // [tap(ic*9+k)][oc]
    __shared__ __align__(16) float sb[64];
    __shared__ __align__(16) float sin_[TT][TY1+2][TX1+2];

    int b  = blockIdx.z;
    int x0 = blockIdx.x * TX1;
    int y0 = blockIdx.y * TY1;
    int tid = threadIdx.x;

    for (int i = tid; i < 45*64; i += 256) {
        int oc = i & 63, kt = i >> 6;
        sw[i] = W1[oc*45 + kt];
    }
    if (tid < 64) sb[tid] = b1[tid];

    for (int i = tid; i < TT*(TY1+2)*(TX1+2); i += 256) {
        int c  = i / ((TY1+2)*(TX1+2));
        int rr = i % ((TY1+2)*(TX1+2));
        int yy = rr / (TX1+2);
        int xx = rr % (TX1+2);
        int gy = y0 + yy - 1;
        int gx = x0 + xx - 1;
        float v = 0.0f;
        if (gy >= 0 && gy < NXX && gx >= 0 && gx < NYY)
            v = in[(b*TT + c)*PLANE + gy*NYY + gx];
        sin_[c][yy][xx] = v;
    }
    __syncthreads();

    int tx = tid & 31;
    int ty = tid >> 5;

    ull acc2[32];
    {
        const ull* sb2 = (const ull*)sb;
        #pragma unroll
        for (int o = 0; o < 32; o++) acc2[o] = sb2[o];
    }

    #pragma unroll 1
    for (int c = 0; c < TT; c++) {
        #pragma unroll
        for (int ky = 0; ky < 3; ky++) {
            #pragma unroll
            for (int kx = 0; kx < 3; kx++) {
                float v = sin_[c][ty+ky][tx+kx];
                ull vv;
                PACK2(vv, __float_as_uint(v), __float_as_uint(v));
                const ulonglong2* w4 = (const ulonglong2*)&sw[(c*9 + ky*3 + kx) << 6];
                #pragma unroll
                for (int o = 0; o < 16; o++) {
                    ulonglong2 wp = w4[o];
                    FMA2(acc2[2*o+0], wp.x, vv, acc2[2*o+0]);
                    FMA2(acc2[2*o+1], wp.y, vv, acc2[2*o+1]);
                }
            }
        }
    }

    int gy = y0 + ty, gx = x0 + tx;
    float* ob = out + b*HID*PLANE + gy*NYY + gx;
    #pragma unroll
    for (int o = 0; o < 32; o++) {
        unsigned int lo, hi;
        UNPACK2(lo, hi, acc2[o]);
        ob[(2*o+0)*PLANE] = fmaxf(__uint_as_float(lo), 0.0f);
        ob[(2*o+1)*PLANE] = fmaxf(__uint_as_float(hi), 0.0f);
    }
}

// ---------------- conv2: [B,64,H,W] -> conv3x3 + b2 -> [B,5,H,W] (+mask fuse)
// FFMA2 over paired x-adjacent pixels: each thread computes 2 pixels, acc2[5].
#define TX2P 64            // pixels per block in x (32 threads x 2 px)
#define TY2 4
#define ICC 16
#define ROWW 68            // padded smem row width (66 used), keeps 8B alignment
__global__ __launch_bounds__(128)
void conv2_kernel(const float* __restrict__ hid,
                  const float* __restrict__ W2,    // [5,64,3,3]
                  const float* __restrict__ b2,    // [5]
                  const float* __restrict__ yobs,
                  const int*   __restrict__ mask,
                  float* __restrict__ out,
                  int apply_mask)
{
    __shared__ __align__(16) ull   sw2[576*6];          // dup weight pairs, 48B/tap
    __shared__ __align__(16) float sinb[ICC*6*ROWW];    // input tile chunk

    int b  = blockIdx.z;
    int x0 = blockIdx.x * TX2P;
    int y0 = blockIdx.y * TY2;
    int tid = threadIdx.x;

    for (int i = tid; i < 576*5; i += 128) {
        int kt = i / 5, oc = i - kt*5;
        float wv = W2[oc*576 + kt];
        ull dup;
        PACK2(dup, __float_as_uint(wv), __float_as_uint(wv));
        sw2[kt*6 + oc] = dup;
    }

    ull acc2[5];
    #pragma unroll
    for (int o = 0; o < 5; o++) {
        float bv = b2[o];
        PACK2(acc2[o], __float_as_uint(bv), __float_as_uint(bv));
    }

    int tx = tid & 31;           // 0..31 -> pixel pair
    int ty = tid >> 5;           // 0..3

    for (int c0 = 0; c0 < HID; c0 += ICC) {
        __syncthreads();
        for (int i = tid; i < ICC*6*(TX2P+2); i += 128) {
            int c  = i / (6*(TX2P+2));
            int rr = i % (6*(TX2P+2));
            int yy = rr / (TX2P+2);
            int xx = rr % (TX2P+2);
            int gy = y0 + yy - 1;
            int gx = x0 + xx - 1;
            float v = 0.0f;
            if (gy >= 0 && gy < NXX && gx >= 0 && gx < NYY)
                v = hid[(b*HID + c0 + c)*PLANE + gy*NYY + gx];
            sinb[(c*6 + yy)*ROWW + xx] = v;
        }
        __syncthreads();

        #pragma unroll 1
        for (int c = 0; c < ICC; c++) {
            #pragma unroll
            for (int ky = 0; ky < 3; ky++) {
                const float* srow = &sinb[(c*6 + ty + ky)*ROWW + 2*tx];
                ull u0 = *(const ull*)(srow);
                ull u1 = *(const ull*)(srow + 2);
                unsigned int a0, a1, b0, b1_;
                UNPACK2(a0, a1, u0);
                UNPACK2(b0, b1_, u1);
                ull mid;
                PACK2(mid, a1, b0);
                ull pix[3] = {u0, mid, u1};
                #pragma unroll
                for (int kx = 0; kx < 3; kx++) {
                    const ull* wt = &sw2[((c0 + c)*9 + ky*3 + kx)*6];
                    ulonglong2 wa = *(const ulonglong2*)(wt);
                    ulonglong2 wb = *(const ulonglong2*)(wt + 2);
                    ull        wc = wt[4];
                    ull p = pix[kx];
                    FMA2(acc2[0], wa.x, p, acc2[0]);
                    FMA2(acc2[1], wa.y, p, acc2[1]);
                    FMA2(acc2[2], wb.x, p, acc2[2]);
                    FMA2(acc2[3], wb.y, p, acc2[3]);
                    FMA2(acc2[4], wc,   p, acc2[4]);
                }
            }
        }
    }

    int gy = y0 + ty;
    int gx = x0 + 2*tx;
    int base = b*NPB + gy*NYY + gx;
    #pragma unroll
    for (int o = 0; o < 5; o++) {
        unsigned int lo, hi;
        UNPACK2(lo, hi, acc2[o]);
        float v0 = __uint_as_float(lo);
        float v1 = __uint_as_float(hi);
        int i0 = base + o*PLANE;
        int i1 = i0 + 1;
        if (apply_mask) {
            float m0 = (float)mask[i0];
            float m1 = (float)mask[i1];
            v0 = v0*(1.0f - m0) + yobs[i0]*m0;
            v1 = v1*(1.0f - m1) + yobs[i1]*m1;
        }
        out[i0] = v0;
        out[i1] = v1;
    }
}

// ---------------- finalize cmp_loss [B, NFP+1, 2] ----------------------------
__global__ void finalize_kernel(float* __restrict__ cmp)
{
    int i = threadIdx.x;
    if (i < BB*(NFP+1)*2) {
        int b = i / ((NFP+1)*2);
        int r = (i / 2) % (NFP+1);
        int c = i & 1;
        double v = g_acc[b][r][c];
        if (c == 0) v /= (double)NPB;       // mean for MSE
        cmp[i] = (float)v;
    }
}

// ---------------- launcher ---------------------------------------------------
extern "C" void kernel_launch(void* const* d_in, const int* in_sizes, int n_in,
                              void* d_out, int out_size)
{
    const float* gt   = (const float*)d_in[0];
    const float* x    = (const float*)d_in[1];
    const float* yobs = (const float*)d_in[2];
    const int*   mask = (const int*)  d_in[3];
    const float* W1   = (const float*)d_in[4];
    const float* b1   = (const float*)d_in[5];
    const float* W2   = (const float*)d_in[6];
    const float* b2   = (const float*)d_in[7];
    (void)in_sizes; (void)n_in;

    float* out     = (float*)d_out;
    float* out_x   = out;                                  // [B,5,512,512]
    float* out_cmp = out + (out_size - BB*(NFP+1)*2);      // [B,NFP+1,2]

    void *p0, *p1, *p2;
    cudaGetSymbolAddress(&p0, g_xbuf);
    cudaGetSymbolAddress(&p1, g_hid);
    cudaGetSymbolAddress(&p2, g_acc);
    float* xb0 = (float*)p0;
    float* xb1 = xb0 + FIELD;
    float* hid = (float*)p1;

    cudaMemsetAsync(p2, 0, sizeof(double)*BB*(NFP+1)*2);
    cudaMemcpyAsync(xb0, x, sizeof(float)*FIELD, cudaMemcpyDeviceToDevice);

    dim3 cgrid(NPB/4/256, BB);        // (1280, 4), exact
    dim3 g1(NYY/TX1, NXX/TY1, BB);    // (16, 64, 4)
    dim3 g2(NYY/TX2P, NXX/TY2, BB);   // (8, 128, 4)

    float* cur = xb0;
    float* nxt = xb1;
    for (int k = 0; k < NFP; k++) {
        cost_kernel<<<cgrid, 256>>>(cur, gt, yobs, mask, k);
        conv1_kernel<<<g1, 256>>>(cur, W1, b1, hid);
        conv2_kernel<<<g2, 128>>>(hid, W2, b2, yobs, mask, nxt, 1);
        float* tmp = cur; cur = nxt; nxt = tmp;
    }
    // final phi (no mask blend), straight into d_out
    conv1_kernel<<<g1, 256>>>(cur, W1, b1, hid);
    conv2_kernel<<<g2, 128>>>(hid, W2, b2, yobs, mask, out_x, 0);
    cost_kernel<<<cgrid, 256>>>(out_x, gt, yobs, mask, NFP);
    finalize_kernel<<<1, 64>>>(out_cmp);
}

// round 8
// speedup vs baseline: 1.5882x; 1.4428x over previous
#include <cuda_runtime.h>
#include <cuda_bf16.h>

#define BB 4
#define TT 5
#define NXX 512
#define NYY 512
#define HID 64
#define NFP 4
#define PLANE (NXX*NYY)          // 262144 = 2^18
#define NPB (TT*PLANE)           // 1310720 elements per batch
#define FIELD (BB*NPB)           // 5242880

typedef unsigned long long ull;

// packed fp32x2 FMA (Blackwell-only; ptxas never auto-fuses this)
#define FMA2(d, a, b, c) \
    asm("fma.rn.f32x2 %0, %1, %2, %3;" : "=l"(d) : "l"(a), "l"(b), "l"(c))
#define PACK2(out, lo, hi) \
    asm("mov.b64 %0, {%1, %2};" : "=l"(out) : "r"(lo), "r"(hi))
#define UNPACK2(lo, hi, in) \
    asm("mov.b64 {%0, %1}, %2;" : "=r"(lo), "=r"(hi) : "l"(in))

// ---------------- scratch (static device globals; no allocation) -------------
__device__ float  g_xbuf[2][FIELD];             // ping-pong x_k  (~42 MB)
__device__ float  g_hid[BB*HID*PLANE];          // hidden activations (~268 MB)
__device__ double g_acc[BB][NFP+1][2];          // cost accumulators

// shifts the ncu -s 5 capture window so launch #5 = conv2_kernel
__global__ void dummy_kernel() {}

// ---------------- cost row: mse + (dy_term + x^T Q x) ------------------------
__global__ __launch_bounds__(256)
void cost_kernel(const float* __restrict__ x,
                 const float* __restrict__ gt,
                 const float* __restrict__ yobs,
                 const int*   __restrict__ mask,
                 int row)
{
    int b = blockIdx.y;
    const float* xb = x + b*NPB;
    int j = blockIdx.x*256 + threadIdx.x;     // float4 group index, exact grid

    float s_mse = 0.0f, s_oi = 0.0f;
    {
        int i  = j << 2;
        int t  = i >> 18;
        int ix = (i >> 9) & 511;
        int iy = i & 511;
        const float4 z4 = make_float4(0.f, 0.f, 0.f, 0.f);

        float4 xv = ((const float4*)xb)[j];
        float4 gv = ((const float4*)(gt   + b*NPB))[j];
        float4 yv = ((const float4*)(yobs + b*NPB))[j];
        int4   mv = ((const int4*)(mask + b*NPB))[j];
        float4 xd = (ix < NXX-1) ? ((const float4*)xb)[j + NYY/4]     : z4;
        float4 xt = (t  < TT-1)  ? ((const float4*)xb)[j + PLANE/4]   : z4;
        float nxt = (iy != NYY-4) ? xb[i + 4] : 0.0f;

        float xa[4] = {xv.x, xv.y, xv.z, xv.w};
        float ga[4] = {gv.x, gv.y, gv.z, gv.w};
        float ya[4] = {yv.x, yv.y, yv.z, yv.w};
        float ma[4] = {(float)mv.x, (float)mv.y, (float)mv.z, (float)mv.w};
        float da[4] = {xd.x, xd.y, xd.z, xd.w};
        float ta[4] = {xt.x, xt.y, xt.z, xt.w};
        float ra[4] = {xv.y, xv.z, xv.w, nxt};

        #pragma unroll
        for (int e = 0; e < 4; e++) {
            float g = ga[e] - xa[e];
            s_mse += g*g;
            float d  = xa[e] - ya[e];
            float nb = ra[e] + da[e] + ta[e];
            s_oi += 1000.0f*ma[e]*d*d + 6.01f*xa[e]*xa[e] - 2.0f*xa[e]*nb;
        }
    }

    double dm = (double)s_mse, doi = (double)s_oi;
    #pragma unroll
    for (int off = 16; off; off >>= 1) {
        dm  += __shfl_down_sync(0xffffffffu, dm,  off);
        doi += __shfl_down_sync(0xffffffffu, doi, off);
    }
    __shared__ double red[2][8];
    int lane = threadIdx.x & 31, w = threadIdx.x >> 5;
    if (lane == 0) { red[0][w] = dm; red[1][w] = doi; }
    __syncthreads();
    if (threadIdx.x == 0) {
        double a = 0.0, c = 0.0;
        #pragma unroll
        for (int i2 = 0; i2 < 8; i2++) { a += red[0][i2]; c += red[1][i2]; }
        atomicAdd(&g_acc[b][row][0], a);
        atomicAdd(&g_acc[b][row][1], c);
    }
}

// ---------------- conv1: [B,5,H,W] -> relu(conv3x3 + b1) -> [B,64,H,W] -------
// Warp-half oc split (32 oc = 16 pairs) x 2 y-adjacent pixels per thread.
// Per tap: 8 LDS.128 weights + 2 scalar pixels feed 32 FFMA2.
#define TX1 32
#define TY1 8                    // output rows per block
__global__ __launch_bounds__(256, 2)
void conv1_kernel(const float* __restrict__ in,
                  const float* __restrict__ W1,   // [64,5,3,3]
                  const float* __restrict__ b1,   // [64]
                  float* __restrict__ out)        // [B,64,H,W]
{
    __shared__ __align__(16) float sw[45*64];     // [tap(ic*9+k)][oc]
    __shared__ __align__(16) float sb[64];
    __shared__ __align__(16) float sin_[TT][TY1+2][TX1+2];

    int b  = blockIdx.z;
    int x0 = blockIdx.x * TX1;
    int y0 = blockIdx.y * TY1;
    int tid = threadIdx.x;

    for (int i = tid; i < 45*64; i += 256) {
        int oc = i & 63, kt = i >> 6;
        sw[i] = W1[oc*45 + kt];
    }
    if (tid < 64) sb[tid] = b1[tid];

    for (int i = tid; i < TT*(TY1+2)*(TX1+2); i += 256) {
        int c  = i / ((TY1+2)*(TX1+2));
        int rr = i % ((TY1+2)*(TX1+2));
        int yy = rr / (TX1+2);
        int xx = rr % (TX1+2);
        int gy = y0 + yy - 1;
        int gx = x0 + xx - 1;
        float v = 0.0f;
        if (gy >= 0 && gy < NXX && gx >= 0 && gx < NYY)
            v = in[(b*TT + c)*PLANE + gy*NYY + gx];
        sin_[c][yy][xx] = v;
    }
    __syncthreads();

    int tx  = tid & 31;
    int q   = tid >> 5;          // 0..7
    int ty  = q >> 1;            // 0..3  -> output rows 2ty, 2ty+1
    int och = q & 1;             // oc half: [och*32, och*32+32)

    ull acc2[2][16];
    {
        const ull* sb2 = (const ull*)sb;          // 32 oc-pairs
        #pragma unroll
        for (int o = 0; o < 16; o++) {
            ull bv = sb2[och*16 + o];
            acc2[0][o] = bv;
            acc2[1][o] = bv;
        }
    }

    #pragma unroll 1
    for (int c = 0; c < TT; c++) {
        #pragma unroll
        for (int ky = 0; ky < 3; ky++) {
            #pragma unroll
            for (int kx = 0; kx < 3; kx++) {
                float v0 = sin_[c][2*ty + ky    ][tx+kx];
                float v1 = sin_[c][2*ty + ky + 1][tx+kx];
                ull vv0, vv1;
                PACK2(vv0, __float_as_uint(v0), __float_as_uint(v0));
                PACK2(vv1, __float_as_uint(v1), __float_as_uint(v1));
                const ulonglong2* w4 =
                    (const ulonglong2*)&sw[((c*9 + ky*3 + kx) << 6) + och*32];
                #pragma unroll
                for (int o = 0; o < 8; o++) {
                    ulonglong2 wp = w4[o];
                    FMA2(acc2[0][2*o+0], wp.x, vv0, acc2[0][2*o+0]);
                    FMA2(acc2[0][2*o+1], wp.y, vv0, acc2[0][2*o+1]);
                    FMA2(acc2[1][2*o+0], wp.x, vv1, acc2[1][2*o+0]);
                    FMA2(acc2[1][2*o+1], wp.y, vv1, acc2[1][2*o+1]);
                }
            }
        }
    }

    int gy = y0 + 2*ty, gx = x0 + tx;
    float* ob = out + (size_t)b*HID*PLANE + gy*NYY + gx;
    #pragma unroll
    for (int o = 0; o < 16; o++) {
        int oc = och*32 + 2*o;
        unsigned int lo, hi;
        UNPACK2(lo, hi, acc2[0][o]);
        ob[ oc   *PLANE] = fmaxf(__uint_as_float(lo), 0.0f);
        ob[(oc+1)*PLANE] = fmaxf(__uint_as_float(hi), 0.0f);
        UNPACK2(lo, hi, acc2[1][o]);
        ob[ oc   *PLANE + NYY] = fmaxf(__uint_as_float(lo), 0.0f);
        ob[(oc+1)*PLANE + NYY] = fmaxf(__uint_as_float(hi), 0.0f);
    }
}

// ---------------- conv2: [B,64,H,W] -> conv3x3 + b2 -> [B,5,H,W] (+mask fuse)
// 4 pixel-pairs (8 px) per thread; weights for each (c,ky) hoisted into regs
// once and reused across the 4 pairs.
#define CTX 256            // pixels per block in x
#define CTY 4              // rows per block
#define CICC 4             // channels per smem chunk
#define ROWW 268           // padded row (258 used: idx 3..260), 16B-aligned
__global__ __launch_bounds__(128)
void conv2_kernel(const float* __restrict__ hid,
                  const float* __restrict__ W2,    // [5,64,3,3]
                  const float* __restrict__ b2,    // [5]
                  const float* __restrict__ yobs,
                  const int*   __restrict__ mask,
                  float* __restrict__ out,
                  int apply_mask)
{
    __shared__ __align__(16) ull   sw2[576*6];          // dup weight pairs 27.6KB
    __shared__ __align__(16) float sinb[CICC*6*ROWW];   // 25.7KB

    int b  = blockIdx.z;
    int x0 = blockIdx.x * CTX;
    int y0 = blockIdx.y * CTY;
    int tid = threadIdx.x;

    for (int i = tid; i < 576*5; i += 128) {
        int kt = i / 5, oc = i - kt*5;
        float wv = W2[oc*576 + kt];
        ull dup;
        PACK2(dup, __float_as_uint(wv), __float_as_uint(wv));
        sw2[kt*6 + oc] = dup;
    }

    ull acc2[4][5];
    #pragma unroll
    for (int o = 0; o < 5; o++) {
        float bv = b2[o];
        ull dup;
        PACK2(dup, __float_as_uint(bv), __float_as_uint(bv));
        #pragma unroll
        for (int g = 0; g < 4; g++) acc2[g][o] = dup;
    }

    int tx = tid & 31;           // pixel-pair lane
    int ty = tid >> 5;           // 0..3

    #pragma unroll 1
    for (int c0 = 0; c0 < HID; c0 += CICC) {
        __syncthreads();
        // interior: float4-aligned (smem idx = gx - x0 + 4; interior always in-bounds in x)
        for (int i = tid; i < CICC*6*64; i += 128) {
            int r  = i >> 6;            // 0..23 : (c,yy)
            int v  = i & 63;
            int c  = r / 6;
            int yy = r - c*6;
            int gy = y0 + yy - 1;
            float4 val = make_float4(0.f,0.f,0.f,0.f);
            if (gy >= 0 && gy < NXX)
                val = *(const float4*)&hid[(size_t)(b*HID + c0 + c)*PLANE
                                           + gy*NYY + x0 + 4*v];
            *(float4*)&sinb[(c*6 + yy)*ROWW + 4*v + 4] = val;
        }
        // halo columns (gx = x0-1 at idx 3, gx = x0+256 at idx 260)
        for (int i = tid; i < CICC*6*2; i += 128) {
            int r  = i >> 1;
            int s  = i & 1;
            int c  = r / 6;
            int yy = r - c*6;
            int gy = y0 + yy - 1;
            int gx = s ? (x0 + CTX) : (x0 - 1);
            float v = 0.0f;
            if (gy >= 0 && gy < NXX && gx >= 0 && gx < NYY)
                v = hid[(size_t)(b*HID + c0 + c)*PLANE + gy*NYY + gx];
            sinb[(c*6 + yy)*ROWW + (s ? 260 : 3)] = v;
        }
        __syncthreads();

        #pragma unroll
        for (int c = 0; c < CICC; c++) {
            #pragma unroll
            for (int ky = 0; ky < 3; ky++) {
                // hoist weights for 3 kx taps (15 dup-pairs)
                int tap0 = ((c0 + c)*9 + ky*3)*6;
                ulonglong2 wA0 = *(const ulonglong2*)&sw2[tap0 +  0];
                ulonglong2 wB0 = *(const ulonglong2*)&sw2[tap0 +  2];
                ull        wC0 = sw2[tap0 + 4];
                ulonglong2 wA1 = *(const ulonglong2*)&sw2[tap0 +  6];
                ulonglong2 wB1 = *(const ulonglong2*)&sw2[tap0 +  8];
                ull        wC1 = sw2[tap0 + 10];
                ulonglong2 wA2 = *(const ulonglong2*)&sw2[tap0 + 12];
                ulonglong2 wB2 = *(const ulonglong2*)&sw2[tap0 + 14];
                ull        wC2 = sw2[tap0 + 16];

                const float* srow = &sinb[(c*6 + ty + ky)*ROWW];
                #pragma unroll
                for (int g = 0; g < 4; g++) {
                    int xb = 2*tx + 64*g;            // pair base (gx - x0)
                    ull   u  = *(const ull*)&srow[xb + 4];   // (p0, p1)
                    float sl = srow[xb + 3];                 // p-1
                    float sr = srow[xb + 6];                 // p2
                    unsigned int ulo, uhi;
                    UNPACK2(ulo, uhi, u);
                    ull p0, p2;
                    PACK2(p0, __float_as_uint(sl), ulo);     // (p-1, p0)
                    PACK2(p2, uhi, __float_as_uint(sr));     // (p1,  p2)

                    FMA2(acc2[g][0], wA0.x, p0, acc2[g][0]);
                    FMA2(acc2[g][1], wA0.y, p0, acc2[g][1]);
                    FMA2(acc2[g][2], wB0.x, p0, acc2[g][2]);
                    FMA2(acc2[g][3], wB0.y, p0, acc2[g][3]);
                    FMA2(acc2[g][4], wC0,   p0, acc2[g][4]);

                    FMA2(acc2[g][0], wA1.x, u,  acc2[g][0]);
                    FMA2(acc2[g][1], wA1.y, u,  acc2[g][1]);
                    FMA2(acc2[g][2], wB1.x, u,  acc2[g][2]);
                    FMA2(acc2[g][3], wB1.y, u,  acc2[g][3]);
                    FMA2(acc2[g][4], wC1,   u,  acc2[g][4]);

                    FMA2(acc2[g][0], wA2.x, p2, acc2[g][0]);
                    FMA2(acc2[g][1], wA2.y, p2, acc2[g][1]);
                    FMA2(acc2[g][2], wB2.x, p2, acc2[g][2]);
                    FMA2(acc2[g][3], wB2.y, p2, acc2[g][3]);
                    FMA2(acc2[g][4], wC2,   p2, acc2[g][4]);
                }
            }
        }
    }

    int gy = y0 + ty;
    #pragma unroll
    for (int g = 0; g < 4; g++) {
        int gx   = x0 + 2*tx + 64*g;
        int base = b*NPB + gy*NYY + gx;
        #pragma unroll
        for (int o = 0; o < 5; o++) {
            unsigned int lo, hi;
            UNPACK2(lo, hi, acc2[g][o]);
            float v0 = __uint_as_float(lo);
            float v1 = __uint_as_float(hi);
            int i0 = base + o*PLANE;
            int i1 = i0 + 1;
            if (apply_mask) {
                float m0 = (float)mask[i0];
                float m1 = (float)mask[i1];
                v0 = v0*(1.0f - m0) + yobs[i0]*m0;
                v1 = v1*(1.0f - m1) + yobs[i1]*m1;
            }
            out[i0] = v0;
            out[i1] = v1;
        }
    }
}

// ---------------- finalize cmp_loss [B, NFP+1, 2] ----------------------------
__global__ void finalize_kernel(float* __restrict__ cmp)
{
    int i = threadIdx.x;
    if (i < BB*(NFP+1)*2) {
        int b = i / ((NFP+1)*2);
        int r = (i / 2) % (NFP+1);
        int c = i & 1;
        double v = g_acc[b][r][c];
        if (c == 0) v /= (double)NPB;       // mean for MSE
        cmp[i] = (float)v;
    }
}

// ---------------- launcher ---------------------------------------------------
extern "C" void kernel_launch(void* const* d_in, const int* in_sizes, int n_in,
                              void* d_out, int out_size)
{
    const float* gt   = (const float*)d_in[0];
    const float* x    = (const float*)d_in[1];
    const float* yobs = (const float*)d_in[2];
    const int*   mask = (const int*)  d_in[3];
    const float* W1   = (const float*)d_in[4];
    const float* b1   = (const float*)d_in[5];
    const float* W2   = (const float*)d_in[6];
    const float* b2   = (const float*)d_in[7];
    (void)in_sizes; (void)n_in;

    float* out     = (float*)d_out;
    float* out_x   = out;                                  // [B,5,512,512]
    float* out_cmp = out + (out_size - BB*(NFP+1)*2);      // [B,NFP+1,2]

    void *p0, *p1, *p2;
    cudaGetSymbolAddress(&p0, g_xbuf);
    cudaGetSymbolAddress(&p1, g_hid);
    cudaGetSymbolAddress(&p2, g_acc);
    float* xb0 = (float*)p0;
    float* xb1 = xb0 + FIELD;
    float* hid = (float*)p1;

    cudaMemsetAsync(p2, 0, sizeof(double)*BB*(NFP+1)*2);           // launch #0
    cudaMemcpyAsync(xb0, x, sizeof(float)*FIELD, cudaMemcpyDeviceToDevice); // #1
    dummy_kernel<<<1, 32>>>();                                      // launch #2

    dim3 cgrid(NPB/4/256, BB);        // (1280, 4), exact
    dim3 g1(NYY/TX1, NXX/TY1, BB);    // (16, 64, 4)
    dim3 g2(NYY/CTX, NXX/CTY, BB);    // (2, 128, 4)

    float* cur = xb0;
    float* nxt = xb1;
    for (int k = 0; k < NFP; k++) {
        cost_kernel<<<cgrid, 256>>>(cur, gt, yobs, mask, k);        // #3
        conv1_kernel<<<g1, 256>>>(cur, W1, b1, hid);                // #4
        conv2_kernel<<<g2, 128>>>(hid, W2, b2, yobs, mask, nxt, 1); // #5 <- ncu
        float* tmp = cur; cur = nxt; nxt = tmp;
    }
    // final phi (no mask blend), straight into d_out
    conv1_kernel<<<g1, 256>>>(cur, W1, b1, hid);
    conv2_kernel<<<g2, 128>>>(hid, W2, b2, yobs, mask, out_x, 0);
    cost_kernel<<<cgrid, 256>>>(out_x, gt, yobs, mask, NFP);
    finalize_kernel<<<1, 64>>>(out_cmp);
}

// round 11
// speedup vs baseline: 1.5945x; 1.0040x over previous
#include <cuda_runtime.h>
#include <cuda_bf16.h>

#define BB 4
#define TT 5
#define NXX 512
#define NYY 512
#define HID 64
#define NFP 4
#define PLANE (NXX*NYY)          // 262144 = 2^18
#define NPB (TT*PLANE)           // 1310720 elements per batch
#define FIELD (BB*NPB)           // 5242880

typedef unsigned long long ull;

// packed fp32x2 FMA (Blackwell-only; ptxas never auto-fuses this)
#define FMA2(d, a, b, c) \
    asm("fma.rn.f32x2 %0, %1, %2, %3;" : "=l"(d) : "l"(a), "l"(b), "l"(c))
#define PACK2(out, lo, hi) \
    asm("mov.b64 %0, {%1, %2};" : "=l"(out) : "r"(lo), "r"(hi))
#define UNPACK2(lo, hi, in) \
    asm("mov.b64 {%0, %1}, %2;" : "=r"(lo), "=r"(hi) : "l"(in))

// ---------------- scratch (static device globals; no allocation) -------------
__device__ float  g_xbuf[2][FIELD];             // ping-pong x_k  (~42 MB)
__device__ float  g_hid[BB*HID*PLANE];          // hidden activations (~268 MB)
__device__ double g_acc[BB][NFP+1][2];          // cost accumulators

// shifts the ncu -s 5 capture window so launch #5 = conv2_kernel
__global__ void dummy_kernel() {}

// ---------------- cost row: mse + (dy_term + x^T Q x) ------------------------
// 2 float4 groups per thread for MLP (kernel is latency-bound, issue ~16%)
#define CGRP 163840              // NPB/4/2 groups per half
__global__ __launch_bounds__(256)
void cost_kernel(const float* __restrict__ x,
                 const float* __restrict__ gt,
                 const float* __restrict__ yobs,
                 const int*   __restrict__ mask,
                 int row)
{
    int b = blockIdx.y;
    const float* xb = x + b*NPB;
    int j0 = blockIdx.x*256 + threadIdx.x;

    float s_mse = 0.0f, s_oi = 0.0f;
    #pragma unroll
    for (int g = 0; g < 2; g++) {
        int j  = j0 + g*CGRP;
        int i  = j << 2;
        int t  = i >> 18;
        int ix = (i >> 9) & 511;
        int iy = i & 511;
        const float4 z4 = make_float4(0.f, 0.f, 0.f, 0.f);

        float4 xv = ((const float4*)xb)[j];
        float4 gv = ((const float4*)(gt   + b*NPB))[j];
        float4 yv = ((const float4*)(yobs + b*NPB))[j];
        int4   mv = ((const int4*)(mask + b*NPB))[j];
        float4 xd = (ix < NXX-1) ? ((const float4*)xb)[j + NYY/4]     : z4;
        float4 xt = (t  < TT-1)  ? ((const float4*)xb)[j + PLANE/4]   : z4;
        float nxt = (iy != NYY-4) ? xb[i + 4] : 0.0f;

        float xa[4] = {xv.x, xv.y, xv.z, xv.w};
        float ga[4] = {gv.x, gv.y, gv.z, gv.w};
        float ya[4] = {yv.x, yv.y, yv.z, yv.w};
        float ma[4] = {(float)mv.x, (float)mv.y, (float)mv.z, (float)mv.w};
        float da[4] = {xd.x, xd.y, xd.z, xd.w};
        float ta[4] = {xt.x, xt.y, xt.z, xt.w};
        float ra[4] = {xv.y, xv.z, xv.w, nxt};

        #pragma unroll
        for (int e = 0; e < 4; e++) {
            float gg = ga[e] - xa[e];
            s_mse += gg*gg;
            float d  = xa[e] - ya[e];
            float nb = ra[e] + da[e] + ta[e];
            s_oi += 1000.0f*ma[e]*d*d + 6.01f*xa[e]*xa[e] - 2.0f*xa[e]*nb;
        }
    }

    double dm = (double)s_mse, doi = (double)s_oi;
    #pragma unroll
    for (int off = 16; off; off >>= 1) {
        dm  += __shfl_down_sync(0xffffffffu, dm,  off);
        doi += __shfl_down_sync(0xffffffffu, doi, off);
    }
    __shared__ double red[2][8];
    int lane = threadIdx.x & 31, w = threadIdx.x >> 5;
    if (lane == 0) { red[0][w] = dm; red[1][w] = doi; }
    __syncthreads();
    if (threadIdx.x == 0) {
        double a = 0.0, c = 0.0;
        #pragma unroll
        for (int i2 = 0; i2 < 8; i2++) { a += red[0][i2]; c += red[1][i2]; }
        atomicAdd(&g_acc[b][row][0], a);
        atomicAdd(&g_acc[b][row][1], c);
    }
}

// ---------------- conv1: [B,5,H,W] -> relu(conv3x3 + b1) -> [B,64,H,W] -------
// Warp-half oc split (32 oc = 16 pairs) x 2 y-adjacent pixels per thread.
#define TX1 32
#define TY1 8                    // output rows per block
__global__ __launch_bounds__(256, 2)
void conv1_kernel(const float* __restrict__ in,
                  const float* __restrict__ W1,   // [64,5,3,3]
                  const float* __restrict__ b1,   // [64]
                  float* __restrict__ out)        // [B,64,H,W]
{
    __shared__ __align__(16) float sw[45*64];     // [tap(ic*9+k)][oc]
    __shared__ __align__(16) float sb[64];
    __shared__ __align__(16) float sin_[TT][TY1+2][TX1+2];

    int b  = blockIdx.z;
    int x0 = blockIdx.x * TX1;
    int y0 = blockIdx.y * TY1;
    int tid = threadIdx.x;

    for (int i = tid; i < 45*64; i += 256) {
        int oc = i & 63, kt = i >> 6;
        sw[i] = W1[oc*45 + kt];
    }
    if (tid < 64) sb[tid] = b1[tid];

    for (int i = tid; i < TT*(TY1+2)*(TX1+2); i += 256) {
        int c  = i / ((TY1+2)*(TX1+2));
        int rr = i % ((TY1+2)*(TX1+2));
        int yy = rr / (TX1+2);
        int xx = rr % (TX1+2);
        int gy = y0 + yy - 1;
        int gx = x0 + xx - 1;
        float v = 0.0f;
        if (gy >= 0 && gy < NXX && gx >= 0 && gx < NYY)
            v = in[(b*TT + c)*PLANE + gy*NYY + gx];
        sin_[c][yy][xx] = v;
    }
    __syncthreads();

    int tx  = tid & 31;
    int q   = tid >> 5;          // 0..7
    int ty  = q >> 1;            // 0..3  -> output rows 2ty, 2ty+1
    int och = q & 1;             // oc half: [och*32, och*32+32)

    ull acc2[2][16];
    {
        const ull* sb2 = (const ull*)sb;          // 32 oc-pairs
        #pragma unroll
        for (int o = 0; o < 16; o++) {
            ull bv = sb2[och*16 + o];
            acc2[0][o] = bv;
            acc2[1][o] = bv;
        }
    }

    #pragma unroll 1
    for (int c = 0; c < TT; c++) {
        #pragma unroll
        for (int ky = 0; ky < 3; ky++) {
            #pragma unroll
            for (int kx = 0; kx < 3; kx++) {
                float v0 = sin_[c][2*ty + ky    ][tx+kx];
                float v1 = sin_[c][2*ty + ky + 1][tx+kx];
                ull vv0, vv1;
                PACK2(vv0, __float_as_uint(v0), __float_as_uint(v0));
                PACK2(vv1, __float_as_uint(v1), __float_as_uint(v1));
                const ulonglong2* w4 =
                    (const ulonglong2*)&sw[((c*9 + ky*3 + kx) << 6) + och*32];
                #pragma unroll
                for (int o = 0; o < 8; o++) {
                    ulonglong2 wp = w4[o];
                    FMA2(acc2[0][2*o+0], wp.x, vv0, acc2[0][2*o+0]);
                    FMA2(acc2[0][2*o+1], wp.y, vv0, acc2[0][2*o+1]);
                    FMA2(acc2[1][2*o+0], wp.x, vv1, acc2[1][2*o+0]);
                    FMA2(acc2[1][2*o+1], wp.y, vv1, acc2[1][2*o+1]);
                }
            }
        }
    }

    int gy = y0 + 2*ty, gx = x0 + tx;
    float* ob = out + (size_t)b*HID*PLANE + gy*NYY + gx;
    #pragma unroll
    for (int o = 0; o < 16; o++) {
        int oc = och*32 + 2*o;
        unsigned int lo, hi;
        UNPACK2(lo, hi, acc2[0][o]);
        ob[ oc   *PLANE] = fmaxf(__uint_as_float(lo), 0.0f);
        ob[(oc+1)*PLANE] = fmaxf(__uint_as_float(hi), 0.0f);
        UNPACK2(lo, hi, acc2[1][o]);
        ob[ oc   *PLANE + NYY] = fmaxf(__uint_as_float(lo), 0.0f);
        ob[(oc+1)*PLANE + NYY] = fmaxf(__uint_as_float(hi), 0.0f);
    }
}

// ---------------- conv2 v3: channel-pair interleaved smem + x-sliding --------
// FFMA2 pair dim = (even ch, odd ch). Each thread: 4 consecutive x pixels.
// Inner loop has ZERO pack/unpack; all input taps are aligned LDS.128 windows.
#define CTX 128            // pixels per block in x
#define CTY 4              // rows per block
#define ROWU 132           // ull row stride (130 used: xu 0..129), 16B-aligned
__global__ __launch_bounds__(128, 4)
void conv2_kernel(const float* __restrict__ hid,
                  const float* __restrict__ W2,    // [5,64,3,3]
                  const float* __restrict__ b2,    // [5]
                  const float* __restrict__ yobs,
                  const int*   __restrict__ mask,
                  float* __restrict__ out,
                  int apply_mask)
{
    __shared__ __align__(16) ull s_w[32*9*6];      // [cpair][tap][oc pad6] 13.8KB
    __shared__ __align__(16) ull s_in[2][6][ROWU]; // interleaved ch-pairs 12.7KB

    int b  = blockIdx.z;
    int x0 = blockIdx.x * CTX;
    int y0 = blockIdx.y * CTY;
    int tid = threadIdx.x;

    // weights: s_w[(cpg*9+tap)*6 + oc] = (W2[oc][2cpg][tap], W2[oc][2cpg+1][tap])
    for (int i = tid; i < 32*9*5; i += 128) {
        int oc = i % 5;
        int t  = i / 5;
        int tap = t % 9;
        int cpg = t / 9;
        float wl = W2[oc*576 + (2*cpg  )*9 + tap];
        float wh = W2[oc*576 + (2*cpg+1)*9 + tap];
        ull pw;
        PACK2(pw, __float_as_uint(wl), __float_as_uint(wh));
        s_w[(cpg*9 + tap)*6 + oc] = pw;
    }

    float bias[5];
    #pragma unroll
    for (int o = 0; o < 5; o++) bias[o] = b2[o];

    int tx = tid & 31;           // 4-px group in x
    int ty = tid >> 5;           // 0..3

    ull acc2[4][5];
    #pragma unroll
    for (int p = 0; p < 4; p++)
        #pragma unroll
        for (int o = 0; o < 5; o++) acc2[p][o] = 0ull;

    #pragma unroll 1
    for (int c0b = 0; c0b < HID; c0b += 4) {       // 16 chunks of 2 cpairs
        __syncthreads();
        // interior: 2cp x 6rows x 32 quads of 4 ulls (xu 1..128)
        for (int i = tid; i < 2*6*32; i += 128) {
            int cp = i / (6*32);
            int r  = i % (6*32);
            int yy = r >> 5;
            int q  = r & 31;
            int gy = y0 + yy - 1;
            float4 a = make_float4(0.f,0.f,0.f,0.f);
            float4 c = make_float4(0.f,0.f,0.f,0.f);
            if (gy >= 0 && gy < NXX) {
                const float* pa = hid + (size_t)(b*HID + c0b + 2*cp)*PLANE
                                      + gy*NYY + x0 + 4*q;
                a = *(const float4*)pa;
                c = *(const float4*)(pa + PLANE);
            }
            unsigned da = (unsigned)__cvta_generic_to_shared(&s_in[cp][yy][1 + 4*q]);
            asm volatile("st.shared.v2.b32 [%0], {%1,%2};" :: "r"(da),
                         "r"(__float_as_uint(a.x)), "r"(__float_as_uint(c.x)) : "memory");
            asm volatile("st.shared.v2.b32 [%0], {%1,%2};" :: "r"(da+8),
                         "r"(__float_as_uint(a.y)), "r"(__float_as_uint(c.y)) : "memory");
            asm volatile("st.shared.v2.b32 [%0], {%1,%2};" :: "r"(da+16),
                         "r"(__float_as_uint(a.z)), "r"(__float_as_uint(c.z)) : "memory");
            asm volatile("st.shared.v2.b32 [%0], {%1,%2};" :: "r"(da+24),
                         "r"(__float_as_uint(a.w)), "r"(__float_as_uint(c.w)) : "memory");
        }
        // halo columns: xu=0 (gx=x0-1), xu=129 (gx=x0+CTX)
        if (tid < 24) {
            int cp = tid / 12;
            int r  = tid % 12;
            int yy = r >> 1;
            int s  = r & 1;
            int gy = y0 + yy - 1;
            int gx = s ? (x0 + CTX) : (x0 - 1);
            float va = 0.0f, vc = 0.0f;
            if (gy >= 0 && gy < NXX && gx >= 0 && gx < NYY) {
                const float* pa = hid + (size_t)(b*HID + c0b + 2*cp)*PLANE
                                      + gy*NYY + gx;
                va = pa[0];
                vc = pa[PLANE];
            }
            ull pv;
            PACK2(pv, __float_as_uint(va), __float_as_uint(vc));
            s_in[cp][yy][s ? 129 : 0] = pv;
        }
        __syncthreads();

        #pragma unroll
        for (int cp = 0; cp < 2; cp++) {
            int cpg = (c0b >> 1) + cp;
            #pragma unroll
            for (int ky = 0; ky < 3; ky++) {
                const ull* wt = &s_w[(cpg*9 + ky*3)*6];
                ulonglong2 w0a = *(const ulonglong2*)&wt[0];
                ulonglong2 w0b = *(const ulonglong2*)&wt[2];
                ull        w0c = wt[4];
                ulonglong2 w1a = *(const ulonglong2*)&wt[6];
                ulonglong2 w1b = *(const ulonglong2*)&wt[8];
                ull        w1c = wt[10];
                ulonglong2 w2a = *(const ulonglong2*)&wt[12];
                ulonglong2 w2b = *(const ulonglong2*)&wt[14];
                ull        w2c = wt[16];

                // window xu = 4tx .. 4tx+5 (pixel P=4tx+p: taps xu P..P+2)
                const ulonglong2* rv =
                    (const ulonglong2*)&s_in[cp][ty + ky][4*tx];
                ulonglong2 v01 = rv[0];
                ulonglong2 v23 = rv[1];
                ulonglong2 v45 = rv[2];
                ull v[6] = {v01.x, v01.y, v23.x, v23.y, v45.x, v45.y};

                #pragma unroll
                for (int p = 0; p < 4; p++) {
                    ull p0 = v[p], p1 = v[p+1], p2 = v[p+2];
                    FMA2(acc2[p][0], w0a.x, p0, acc2[p][0]);
                    FMA2(acc2[p][1], w0a.y, p0, acc2[p][1]);
                    FMA2(acc2[p][2], w0b.x, p0, acc2[p][2]);
                    FMA2(acc2[p][3], w0b.y, p0, acc2[p][3]);
                    FMA2(acc2[p][4], w0c,   p0, acc2[p][4]);

                    FMA2(acc2[p][0], w1a.x, p1, acc2[p][0]);
                    FMA2(acc2[p][1], w1a.y, p1, acc2[p][1]);
                    FMA2(acc2[p][2], w1b.x, p1, acc2[p][2]);
                    FMA2(acc2[p][3], w1b.y, p1, acc2[p][3]);
                    FMA2(acc2[p][4], w1c,   p1, acc2[p][4]);

                    FMA2(acc2[p][0], w2a.x, p2, acc2[p][0]);
                    FMA2(acc2[p][1], w2a.y, p2, acc2[p][1]);
                    FMA2(acc2[p][2], w2b.x, p2, acc2[p][2]);
                    FMA2(acc2[p][3], w2b.y, p2, acc2[p][3]);
                    FMA2(acc2[p][4], w2c,   p2, acc2[p][4]);
                }
            }
        }
    }

    // epilogue: out[px][o] = lo + hi + bias  (even-ch + odd-ch partials)
    int gy = y0 + ty;
    int base = b*NPB + gy*NYY + x0 + 4*tx;
    #pragma unroll
    for (int o = 0; o < 5; o++) {
        float r[4];
        #pragma unroll
        for (int p = 0; p < 4; p++) {
            unsigned int lo, hi;
            UNPACK2(lo, hi, acc2[p][o]);
            r[p] = __uint_as_float(lo) + __uint_as_float(hi) + bias[o];
        }
        int idx = base + o*PLANE;
        if (apply_mask) {
            int4   m4 = *(const int4*)&mask[idx];
            float4 y4 = *(const float4*)&yobs[idx];
            r[0] = r[0]*(1.0f - (float)m4.x) + y4.x*(float)m4.x;
            r[1] = r[1]*(1.0f - (float)m4.y) + y4.y*(float)m4.y;
            r[2] = r[2]*(1.0f - (float)m4.z) + y4.z*(float)m4.z;
            r[3] = r[3]*(1.0f - (float)m4.w) + y4.w*(float)m4.w;
        }
        *(float4*)&out[idx] = make_float4(r[0], r[1], r[2], r[3]);
    }
}

// ---------------- finalize cmp_loss [B, NFP+1, 2] ----------------------------
__global__ void finalize_kernel(float* __restrict__ cmp)
{
    int i = threadIdx.x;
    if (i < BB*(NFP+1)*2) {
        int b = i / ((NFP+1)*2);
        int r = (i / 2) % (NFP+1);
        int c = i & 1;
        double v = g_acc[b][r][c];
        if (c == 0) v /= (double)NPB;       // mean for MSE
        cmp[i] = (float)v;
    }
}

// ---------------- launcher ---------------------------------------------------
extern "C" void kernel_launch(void* const* d_in, const int* in_sizes, int n_in,
                              void* d_out, int out_size)
{
    const float* gt   = (const float*)d_in[0];
    const float* x    = (const float*)d_in[1];
    const float* yobs = (const float*)d_in[2];
    const int*   mask = (const int*)  d_in[3];
    const float* W1   = (const float*)d_in[4];
    const float* b1   = (const float*)d_in[5];
    const float* W2   = (const float*)d_in[6];
    const float* b2   = (const float*)d_in[7];
    (void)in_sizes; (void)n_in;

    float* out     = (float*)d_out;
    float* out_x   = out;                                  // [B,5,512,512]
    float* out_cmp = out + (out_size - BB*(NFP+1)*2);      // [B,NFP+1,2]

    void *p0, *p1, *p2;
    cudaGetSymbolAddress(&p0, g_xbuf);
    cudaGetSymbolAddress(&p1, g_hid);
    cudaGetSymbolAddress(&p2, g_acc);
    float* xb0 = (float*)p0;
    float* xb1 = xb0 + FIELD;
    float* hid = (float*)p1;

    cudaMemsetAsync(p2, 0, sizeof(double)*BB*(NFP+1)*2);            // launch #0
    cudaMemcpyAsync(xb0, x, sizeof(float)*FIELD, cudaMemcpyDeviceToDevice); // #1
    dummy_kernel<<<1, 32>>>();                                       // launch #2

    dim3 cgrid(CGRP/256, BB);         // (640, 4), 2 groups/thread, exact
    dim3 g1(NYY/TX1, NXX/TY1, BB);    // (16, 64, 4)
    dim3 g2(NYY/CTX, NXX/CTY, BB);    // (4, 128, 4)

    float* cur = xb0;
    float* nxt = xb1;
    for (int k = 0; k < NFP; k++) {
        cost_kernel<<<cgrid, 256>>>(cur, gt, yobs, mask, k);         // #3
        conv1_kernel<<<g1, 256>>>(cur, W1, b1, hid);                 // #4
        conv2_kernel<<<g2, 128>>>(hid, W2, b2, yobs, mask, nxt, 1);  // #5 <- ncu
        float* tmp = cur; cur = nxt; nxt = tmp;
    }
    // final phi (no mask blend), straight into d_out
    conv1_kernel<<<g1, 256>>>(cur, W1, b1, hid);
    conv2_kernel<<<g2, 128>>>(hid, W2, b2, yobs, mask, out_x, 0);
    cost_kernel<<<cgrid, 256>>>(out_x, gt, yobs, mask, NFP);
    finalize_kernel<<<1, 64>>>(out_cmp);
}

// round 12
// speedup vs baseline: 2.0284x; 1.2721x over previous
#include <cuda_runtime.h>
#include <cuda_bf16.h>

#define BB 4
#define TT 5
#define NXX 512
#define NYY 512
#define HID 64
#define NFP 4
#define PLANE (NXX*NYY)          // 262144 = 2^18
#define NPB (TT*PLANE)           // 1310720 elements per batch
#define FIELD (BB*NPB)           // 5242880

typedef unsigned long long ull;

// packed fp32x2 FMA (Blackwell-only; ptxas never auto-fuses this)
#define FMA2(d, a, b, c) \
    asm("fma.rn.f32x2 %0, %1, %2, %3;" : "=l"(d) : "l"(a), "l"(b), "l"(c))
#define PACK2(out, lo, hi) \
    asm("mov.b64 %0, {%1, %2};" : "=l"(out) : "r"(lo), "r"(hi))
#define UNPACK2(lo, hi, in) \
    asm("mov.b64 {%0, %1}, %2;" : "=r"(lo), "=r"(hi) : "l"(in))

// ---------------- scratch (static device globals; no allocation) -------------
__device__ float  g_xbuf[2][FIELD];             // ping-pong x_k  (~42 MB)
__device__ double g_acc[BB][NFP+1][2];          // cost accumulators

// ---------------- cost row: mse + (dy_term + x^T Q x) ------------------------
#define CGRP 163840              // NPB/4/2 groups per half
__global__ __launch_bounds__(256)
void cost_kernel(const float* __restrict__ x,
                 const float* __restrict__ gt,
                 const float* __restrict__ yobs,
                 const int*   __restrict__ mask,
                 int row)
{
    int b = blockIdx.y;
    const float* xb = x + b*NPB;
    int j0 = blockIdx.x*256 + threadIdx.x;

    float s_mse = 0.0f, s_oi = 0.0f;
    #pragma unroll
    for (int g = 0; g < 2; g++) {
        int j  = j0 + g*CGRP;
        int i  = j << 2;
        int t  = i >> 18;
        int ix = (i >> 9) & 511;
        int iy = i & 511;
        const float4 z4 = make_float4(0.f, 0.f, 0.f, 0.f);

        float4 xv = ((const float4*)xb)[j];
        float4 gv = ((const float4*)(gt   + b*NPB))[j];
        float4 yv = ((const float4*)(yobs + b*NPB))[j];
        int4   mv = ((const int4*)(mask + b*NPB))[j];
        float4 xd = (ix < NXX-1) ? ((const float4*)xb)[j + NYY/4]     : z4;
        float4 xt = (t  < TT-1)  ? ((const float4*)xb)[j + PLANE/4]   : z4;
        float nxt = (iy != NYY-4) ? xb[i + 4] : 0.0f;

        float xa[4] = {xv.x, xv.y, xv.z, xv.w};
        float ga[4] = {gv.x, gv.y, gv.z, gv.w};
        float ya[4] = {yv.x, yv.y, yv.z, yv.w};
        float ma[4] = {(float)mv.x, (float)mv.y, (float)mv.z, (float)mv.w};
        float da[4] = {xd.x, xd.y, xd.z, xd.w};
        float ta[4] = {xt.x, xt.y, xt.z, xt.w};
        float ra[4] = {xv.y, xv.z, xv.w, nxt};

        #pragma unroll
        for (int e = 0; e < 4; e++) {
            float gg = ga[e] - xa[e];
            s_mse += gg*gg;
            float d  = xa[e] - ya[e];
            float nb = ra[e] + da[e] + ta[e];
            s_oi += 1000.0f*ma[e]*d*d + 6.01f*xa[e]*xa[e] - 2.0f*xa[e]*nb;
        }
    }

    double dm = (double)s_mse, doi = (double)s_oi;
    #pragma unroll
    for (int off = 16; off; off >>= 1) {
        dm  += __shfl_down_sync(0xffffffffu, dm,  off);
        doi += __shfl_down_sync(0xffffffffu, doi, off);
    }
    __shared__ double red[2][8];
    int lane = threadIdx.x & 31, w = threadIdx.x >> 5;
    if (lane == 0) { red[0][w] = dm; red[1][w] = doi; }
    __syncthreads();
    if (threadIdx.x == 0) {
        double a = 0.0, c = 0.0;
        #pragma unroll
        for (int i2 = 0; i2 < 8; i2++) { a += red[0][i2]; c += red[1][i2]; }
        atomicAdd(&g_acc[b][row][0], a);
        atomicAdd(&g_acc[b][row][1], c);
    }
}

// ---------------- fused phi: conv1 -> relu -> conv2 (+bias, +mask blend) -----
// Output tile 32x16. Hidden lives ONLY in smem, channel-pair interleaved.
//
// smem partition (dynamic, 82272 B total):
//   sw1  [45 tap][32 ocpair]            ull   11520 B
//   sw2  [32 cpair][9 tap][6 oc-pad]    ull   13824 B
//   shid [8 cpair][18 y][36 x-pad]      ull   41472 B
//   sb1  [32 ocpair]                    ull     256 B
//   sin_ [5 c][20 y][38 x]              float 15200 B
#define FS_SW1   0
#define FS_SW2   (45*32)
#define FS_SHID  (FS_SW2 + 32*9*6)
#define FS_SB1   (FS_SHID + 8*18*36)
#define FS_ULLS  (FS_SB1 + 32)
#define FS_BYTES (FS_ULLS*8 + 5*20*38*4)

__global__ __launch_bounds__(256, 2)
void fused_phi_kernel(const float* __restrict__ in,
                      const float* __restrict__ W1,   // [64,5,3,3]
                      const float* __restrict__ b1,   // [64]
                      const float* __restrict__ W2,   // [5,64,3,3]
                      const float* __restrict__ b2,   // [5]
                      const float* __restrict__ yobs,
                      const int*   __restrict__ mask,
                      float* __restrict__ out,
                      int apply_mask)
{
    extern __shared__ __align__(16) ull smem_u[];
    ull*   sw1  = smem_u + FS_SW1;
    ull*   sw2  = smem_u + FS_SW2;
    ull*   shid = smem_u + FS_SHID;
    ull*   sb1  = smem_u + FS_SB1;
    float* sin_ = (float*)(smem_u + FS_ULLS);

    int b   = blockIdx.z;
    int x0  = blockIdx.x * 32;
    int y0  = blockIdx.y * 16;
    int tid = threadIdx.x;

    // ---- phase 0: weights + bias + input tile ----
    for (int i = tid; i < 45*32; i += 256) {
        int q = i & 31, t = i >> 5;
        ull p;
        PACK2(p, __float_as_uint(W1[(2*q  )*45 + t]),
                 __float_as_uint(W1[(2*q+1)*45 + t]));
        sw1[t*32 + q] = p;
    }
    for (int i = tid; i < 32*9*5; i += 256) {
        int oc = i % 5;
        int r  = i / 5;
        int tap = r % 9;
        int cp  = r / 9;
        ull p;
        PACK2(p, __float_as_uint(W2[oc*576 + (2*cp  )*9 + tap]),
                 __float_as_uint(W2[oc*576 + (2*cp+1)*9 + tap]));
        sw2[(cp*9 + tap)*6 + oc] = p;
    }
    if (tid < 32) {
        ull p;
        PACK2(p, __float_as_uint(b1[2*tid]), __float_as_uint(b1[2*tid+1]));
        sb1[tid] = p;
    }
    for (int i = tid; i < 5*20*38; i += 256) {
        int c  = i / 760;
        int r  = i % 760;
        int yy = r / 38;
        int xx = r % 38;
        int gy = y0 + yy - 2;
        int gx = x0 + xx - 2;
        float v = 0.0f;
        if (gy >= 0 && gy < NXX && gx >= 0 && gx < NYY)
            v = in[(size_t)(b*TT + c)*PLANE + gy*NYY + gx];
        sin_[i] = v;
    }
    float bias2[5];
    #pragma unroll
    for (int o = 0; o < 5; o++) bias2[o] = b2[o];

    // conv2 output accumulators: 2 x-adjacent pixels, 5 oc (packed ch-pairs)
    ull acc2[2][5];
    #pragma unroll
    for (int p = 0; p < 2; p++)
        #pragma unroll
        for (int o = 0; o < 5; o++) acc2[p][o] = 0ull;

    int i2 = tid & 15;           // x pixel-pair (out x = x0 + 2*i2)
    int oy = tid >> 4;           // 0..15

    __syncthreads();

    #pragma unroll 1
    for (int ch = 0; ch < 4; ch++) {     // 4 chunks of 16 hidden channels
        if (ch) __syncthreads();          // prior phase-B reads done

        // ---- phase A: conv1 -> relu -> shid (16 ch = 8 cpairs) ----
        if (tid < 216) {
            int g   = tid % 12;
            int hy  = tid / 12;           // 0..17
            int hx0 = 3*g;                // pixels hx0..hx0+2 (hx<34 stored)

            ull a1[3][8];
            #pragma unroll
            for (int q = 0; q < 8; q++) {
                ull bv = sb1[ch*8 + q];
                a1[0][q] = bv; a1[1][q] = bv; a1[2][q] = bv;
            }

            #pragma unroll 1
            for (int c = 0; c < TT; c++) {
                #pragma unroll
                for (int ky = 0; ky < 3; ky++) {
                    const float* row = &sin_[(c*20 + hy + ky)*38 + hx0];
                    float v0 = row[0], v1 = row[1], v2 = row[2],
                          v3 = row[3], v4 = row[4];
                    float vt[5] = {v0, v1, v2, v3, v4};
                    #pragma unroll
                    for (int kx = 0; kx < 3; kx++) {
                        const ull* wq = &sw1[(c*9 + ky*3 + kx)*32 + ch*8];
                        ulonglong2 w01 = *(const ulonglong2*)&wq[0];
                        ulonglong2 w23 = *(const ulonglong2*)&wq[2];
                        ulonglong2 w45 = *(const ulonglong2*)&wq[4];
                        ulonglong2 w67 = *(const ulonglong2*)&wq[6];
                        #pragma unroll
                        for (int px = 0; px < 3; px++) {
                            float vs = vt[kx + px];
                            ull vv;
                            PACK2(vv, __float_as_uint(vs), __float_as_uint(vs));
                            FMA2(a1[px][0], w01.x, vv, a1[px][0]);
                            FMA2(a1[px][1], w01.y, vv, a1[px][1]);
                            FMA2(a1[px][2], w23.x, vv, a1[px][2]);
                            FMA2(a1[px][3], w23.y, vv, a1[px][3]);
                            FMA2(a1[px][4], w45.x, vv, a1[px][4]);
                            FMA2(a1[px][5], w45.y, vv, a1[px][5]);
                            FMA2(a1[px][6], w67.x, vv, a1[px][6]);
                            FMA2(a1[px][7], w67.y, vv, a1[px][7]);
                        }
                    }
                }
            }

            // store: relu; zero outside the image (conv2 must see zero pad)
            int gyh = y0 + hy - 1;
            bool yok = (gyh >= 0) && (gyh < NXX);
            #pragma unroll
            for (int px = 0; px < 3; px++) {
                int hx = hx0 + px;
                if (hx < 34) {
                    int gxh = x0 + hx - 1;
                    bool ok = yok && (gxh >= 0) && (gxh < NYY);
                    #pragma unroll
                    for (int q = 0; q < 8; q++) {
                        unsigned int lo, hi;
                        UNPACK2(lo, hi, a1[px][q]);
                        float fl = fmaxf(__uint_as_float(lo), 0.0f);
                        float fh = fmaxf(__uint_as_float(hi), 0.0f);
                        if (!ok) { fl = 0.0f; fh = 0.0f; }
                        ull pv;
                        PACK2(pv, __float_as_uint(fl), __float_as_uint(fh));
                        shid[(q*18 + hy)*36 + hx] = pv;
                    }
                }
            }
        }
        __syncthreads();

        // ---- phase B: conv2 accumulate from shid ----
        #pragma unroll 1
        for (int cp = 0; cp < 8; cp++) {
            int cpg = ch*8 + cp;
            #pragma unroll
            for (int ky = 0; ky < 3; ky++) {
                const ull* wt = &sw2[(cpg*9 + ky*3)*6];
                ulonglong2 w0a = *(const ulonglong2*)&wt[0];
                ulonglong2 w0b = *(const ulonglong2*)&wt[2];
                ull        w0c = wt[4];
                ulonglong2 w1a = *(const ulonglong2*)&wt[6];
                ulonglong2 w1b = *(const ulonglong2*)&wt[8];
                ull        w1c = wt[10];
                ulonglong2 w2a = *(const ulonglong2*)&wt[12];
                ulonglong2 w2b = *(const ulonglong2*)&wt[14];
                ull        w2c = wt[16];

                const ull* rv = &shid[(cp*18 + oy + ky)*36 + 2*i2];
                ulonglong2 vA = *(const ulonglong2*)&rv[0];
                ulonglong2 vB = *(const ulonglong2*)&rv[2];
                ull v0 = vA.x, v1 = vA.y, v2 = vB.x, v3 = vB.y;

                // pixel 0: taps v0,v1,v2
                FMA2(acc2[0][0], w0a.x, v0, acc2[0][0]);
                FMA2(acc2[0][1], w0a.y, v0, acc2[0][1]);
                FMA2(acc2[0][2], w0b.x, v0, acc2[0][2]);
                FMA2(acc2[0][3], w0b.y, v0, acc2[0][3]);
                FMA2(acc2[0][4], w0c,   v0, acc2[0][4]);
                FMA2(acc2[0][0], w1a.x, v1, acc2[0][0]);
                FMA2(acc2[0][1], w1a.y, v1, acc2[0][1]);
                FMA2(acc2[0][2], w1b.x, v1, acc2[0][2]);
                FMA2(acc2[0][3], w1b.y, v1, acc2[0][3]);
                FMA2(acc2[0][4], w1c,   v1, acc2[0][4]);
                FMA2(acc2[0][0], w2a.x, v2, acc2[0][0]);
                FMA2(acc2[0][1], w2a.y, v2, acc2[0][1]);
                FMA2(acc2[0][2], w2b.x, v2, acc2[0][2]);
                FMA2(acc2[0][3], w2b.y, v2, acc2[0][3]);
                FMA2(acc2[0][4], w2c,   v2, acc2[0][4]);
                // pixel 1: taps v1,v2,v3
                FMA2(acc2[1][0], w0a.x, v1, acc2[1][0]);
                FMA2(acc2[1][1], w0a.y, v1, acc2[1][1]);
                FMA2(acc2[1][2], w0b.x, v1, acc2[1][2]);
                FMA2(acc2[1][3], w0b.y, v1, acc2[1][3]);
                FMA2(acc2[1][4], w0c,   v1, acc2[1][4]);
                FMA2(acc2[1][0], w1a.x, v2, acc2[1][0]);
                FMA2(acc2[1][1], w1a.y, v2, acc2[1][1]);
                FMA2(acc2[1][2], w1b.x, v2, acc2[1][2]);
                FMA2(acc2[1][3], w1b.y, v2, acc2[1][3]);
                FMA2(acc2[1][4], w1c,   v2, acc2[1][4]);
                FMA2(acc2[1][0], w2a.x, v3, acc2[1][0]);
                FMA2(acc2[1][1], w2a.y, v3, acc2[1][1]);
                FMA2(acc2[1][2], w2b.x, v3, acc2[1][2]);
                FMA2(acc2[1][3], w2b.y, v3, acc2[1][3]);
                FMA2(acc2[1][4], w2c,   v3, acc2[1][4]);
            }
        }
    }

    // ---- epilogue: sum halves + bias, optional mask blend, write 2 px ----
    int oyg  = y0 + oy;
    int oxg  = x0 + 2*i2;
    int base = b*NPB + oyg*NYY + oxg;
    #pragma unroll
    for (int o = 0; o < 5; o++) {
        unsigned int lo, hi;
        UNPACK2(lo, hi, acc2[0][o]);
        float r0 = __uint_as_float(lo) + __uint_as_float(hi) + bias2[o];
        UNPACK2(lo, hi, acc2[1][o]);
        float r1 = __uint_as_float(lo) + __uint_as_float(hi) + bias2[o];
        int idx = base + o*PLANE;
        if (apply_mask) {
            int2   m2 = *(const int2*)&mask[idx];
            float2 y2 = *(const float2*)&yobs[idx];
            float m0 = (float)m2.x, m1 = (float)m2.y;
            r0 = r0*(1.0f - m0) + y2.x*m0;
            r1 = r1*(1.0f - m1) + y2.y*m1;
        }
        *(float2*)&out[idx] = make_float2(r0, r1);
    }
}

// ---------------- finalize cmp_loss [B, NFP+1, 2] ----------------------------
__global__ void finalize_kernel(float* __restrict__ cmp)
{
    int i = threadIdx.x;
    if (i < BB*(NFP+1)*2) {
        int b = i / ((NFP+1)*2);
        int r = (i / 2) % (NFP+1);
        int c = i & 1;
        double v = g_acc[b][r][c];
        if (c == 0) v /= (double)NPB;       // mean for MSE
        cmp[i] = (float)v;
    }
}

// ---------------- launcher ---------------------------------------------------
extern "C" void kernel_launch(void* const* d_in, const int* in_sizes, int n_in,
                              void* d_out, int out_size)
{
    const float* gt   = (const float*)d_in[0];
    const float* x    = (const float*)d_in[1];
    const float* yobs = (const float*)d_in[2];
    const int*   mask = (const int*)  d_in[3];
    const float* W1   = (const float*)d_in[4];
    const float* b1   = (const float*)d_in[5];
    const float* W2   = (const float*)d_in[6];
    const float* b2   = (const float*)d_in[7];
    (void)in_sizes; (void)n_in;

    float* out     = (float*)d_out;
    float* out_x   = out;                                  // [B,5,512,512]
    float* out_cmp = out + (out_size - BB*(NFP+1)*2);      // [B,NFP+1,2]

    void *p0, *p2;
    cudaGetSymbolAddress(&p0, g_xbuf);
    cudaGetSymbolAddress(&p2, g_acc);
    float* xb0 = (float*)p0;
    float* xb1 = xb0 + FIELD;

    cudaFuncSetAttribute(fused_phi_kernel,
                         cudaFuncAttributeMaxDynamicSharedMemorySize, FS_BYTES);

    cudaMemsetAsync(p2, 0, sizeof(double)*BB*(NFP+1)*2);            // launch #0
    cudaMemcpyAsync(xb0, x, sizeof(float)*FIELD, cudaMemcpyDeviceToDevice); // #1

    dim3 cgrid(CGRP/256, BB);         // (640, 4)
    dim3 gf(NYY/32, NXX/16, BB);      // (16, 32, 4)

    float* cur = xb0;
    float* nxt = xb1;
    for (int k = 0; k < NFP; k++) {
        cost_kernel<<<cgrid, 256>>>(cur, gt, yobs, mask, k);         // #2,...
        fused_phi_kernel<<<gf, 256, FS_BYTES>>>(cur, W1, b1, W2, b2,
                                                yobs, mask, nxt, 1); // #3, #5<-ncu
        float* tmp = cur; cur = nxt; nxt = tmp;
    }
    // final phi (no mask blend), straight into d_out
    fused_phi_kernel<<<gf, 256, FS_BYTES>>>(cur, W1, b1, W2, b2,
                                            yobs, mask, out_x, 0);
    cost_kernel<<<cgrid, 256>>>(out_x, gt, yobs, mask, NFP);
    finalize_kernel<<<1, 64>>>(out_cmp);
}

// round 13
// speedup vs baseline: 2.1288x; 1.0495x over previous
#include <cuda_runtime.h>
#include <cuda_bf16.h>

#define BB 4
#define TT 5
#define NXX 512
#define NYY 512
#define HID 64
#define NFP 4
#define PLANE (NXX*NYY)          // 262144 = 2^18
#define NPB (TT*PLANE)           // 1310720 elements per batch
#define FIELD (BB*NPB)           // 5242880

typedef unsigned long long ull;

// packed fp32x2 FMA (Blackwell-only; ptxas never auto-fuses this)
#define FMA2(d, a, b, c) \
    asm("fma.rn.f32x2 %0, %1, %2, %3;" : "=l"(d) : "l"(a), "l"(b), "l"(c))
#define PACK2(out, lo, hi) \
    asm("mov.b64 %0, {%1, %2};" : "=l"(out) : "r"(lo), "r"(hi))
#define UNPACK2(lo, hi, in) \
    asm("mov.b64 {%0, %1}, %2;" : "=r"(lo), "=r"(hi) : "l"(in))

// ---------------- scratch (static device globals; no allocation) -------------
__device__ float  g_xbuf[2][FIELD];             // ping-pong x_k  (~42 MB)
__device__ double g_acc[BB][NFP+1][2];          // cost accumulators

// ---------------- standalone cost (row NFP only: cost of final phi output) ---
#define CGRP 163840              // NPB/4/2 groups per half
__global__ __launch_bounds__(256)
void cost_kernel(const float* __restrict__ x,
                 const float* __restrict__ gt,
                 const float* __restrict__ yobs,
                 const int*   __restrict__ mask,
                 int row)
{
    int b = blockIdx.y;
    const float* xb = x + b*NPB;
    int j0 = blockIdx.x*256 + threadIdx.x;

    float s_mse = 0.0f, s_oi = 0.0f;
    #pragma unroll
    for (int g = 0; g < 2; g++) {
        int j  = j0 + g*CGRP;
        int i  = j << 2;
        int t  = i >> 18;
        int ix = (i >> 9) & 511;
        int iy = i & 511;
        const float4 z4 = make_float4(0.f, 0.f, 0.f, 0.f);

        float4 xv = ((const float4*)xb)[j];
        float4 gv = ((const float4*)(gt   + b*NPB))[j];
        float4 yv = ((const float4*)(yobs + b*NPB))[j];
        int4   mv = ((const int4*)(mask + b*NPB))[j];
        float4 xd = (ix < NXX-1) ? ((const float4*)xb)[j + NYY/4]     : z4;
        float4 xt = (t  < TT-1)  ? ((const float4*)xb)[j + PLANE/4]   : z4;
        float nxt = (iy != NYY-4) ? xb[i + 4] : 0.0f;

        float xa[4] = {xv.x, xv.y, xv.z, xv.w};
        float ga[4] = {gv.x, gv.y, gv.z, gv.w};
        float ya[4] = {yv.x, yv.y, yv.z, yv.w};
        float ma[4] = {(float)mv.x, (float)mv.y, (float)mv.z, (float)mv.w};
        float da[4] = {xd.x, xd.y, xd.z, xd.w};
        float ta[4] = {xt.x, xt.y, xt.z, xt.w};
        float ra[4] = {xv.y, xv.z, xv.w, nxt};

        #pragma unroll
        for (int e = 0; e < 4; e++) {
            float gg = ga[e] - xa[e];
            s_mse += gg*gg;
            float d  = xa[e] - ya[e];
            float nb = ra[e] + da[e] + ta[e];
            s_oi += 1000.0f*ma[e]*d*d + 6.01f*xa[e]*xa[e] - 2.0f*xa[e]*nb;
        }
    }

    double dm = (double)s_mse, doi = (double)s_oi;
    #pragma unroll
    for (int off = 16; off; off >>= 1) {
        dm  += __shfl_down_sync(0xffffffffu, dm,  off);
        doi += __shfl_down_sync(0xffffffffu, doi, off);
    }
    __shared__ double red[2][8];
    int lane = threadIdx.x & 31, w = threadIdx.x >> 5;
    if (lane == 0) { red[0][w] = dm; red[1][w] = doi; }
    __syncthreads();
    if (threadIdx.x == 0) {
        double a = 0.0, c = 0.0;
        #pragma unroll
        for (int i2 = 0; i2 < 8; i2++) { a += red[0][i2]; c += red[1][i2]; }
        atomicAdd(&g_acc[b][row][0], a);
        atomicAdd(&g_acc[b][row][1], c);
    }
}

// ---------------- fused phi: cost(input) + conv1 -> relu -> conv2 ------------
// Output tile 64x16. Hidden lives ONLY in smem, channel-pair interleaved,
// 8-channel chunks. Phase B: 2 windows of 2 px per thread (weights amortized).
//
// smem partition (dynamic ull base, 92768 B total):
//   sw1  [45 tap][32 ocpair]            ull   11520 B
//   sw2  [32 cpair][9 tap][6 oc-pad]    ull   13824 B
//   shid [4 cpair][18 y][68 x-pad]      ull   39168 B
//   sb1  [32 ocpair]                    ull     256 B
//   sin_ [5 c][20 y][70 x]              float 28000 B
#define FS_SW1   0
#define FS_SW2   (45*32)
#define FS_SHID  (FS_SW2 + 32*9*6)
#define FS_SB1   (FS_SHID + 4*18*68)
#define FS_ULLS  (FS_SB1 + 32)
#define FS_BYTES (FS_ULLS*8 + 5*20*70*4)

__global__ __launch_bounds__(256, 2)
void fused_phi_kernel(const float* __restrict__ in,
                      const float* __restrict__ W1,   // [64,5,3,3]
                      const float* __restrict__ b1,   // [64]
                      const float* __restrict__ W2,   // [5,64,3,3]
                      const float* __restrict__ b2,   // [5]
                      const float* __restrict__ gt,
                      const float* __restrict__ yobs,
                      const int*   __restrict__ mask,
                      float* __restrict__ out,
                      int apply_mask, int cost_row)
{
    extern __shared__ __align__(16) ull smem_u[];
    ull*   sw1   = smem_u + FS_SW1;
    ull*   sw2   = smem_u + FS_SW2;
    ull*   shid  = smem_u + FS_SHID;
    ull*   sb1   = smem_u + FS_SB1;
    float* sin_f = (float*)(smem_u + FS_ULLS);
    __shared__ double red[2][8];

    int b   = blockIdx.z;
    int x0  = blockIdx.x * 64;
    int y0  = blockIdx.y * 16;
    int tid = threadIdx.x;

    // ---- phase 0: weights + bias + input tile ----
    for (int i = tid; i < 45*32; i += 256) {
        int q = i & 31, t = i >> 5;
        ull p;
        PACK2(p, __float_as_uint(W1[(2*q  )*45 + t]),
                 __float_as_uint(W1[(2*q+1)*45 + t]));
        sw1[t*32 + q] = p;
    }
    for (int i = tid; i < 32*9*5; i += 256) {
        int oc = i % 5;
        int r  = i / 5;
        int tap = r % 9;
        int cp  = r / 9;
        ull p;
        PACK2(p, __float_as_uint(W2[oc*576 + (2*cp  )*9 + tap]),
                 __float_as_uint(W2[oc*576 + (2*cp+1)*9 + tap]));
        sw2[(cp*9 + tap)*6 + oc] = p;
    }
    if (tid < 32) {
        ull p;
        PACK2(p, __float_as_uint(b1[2*tid]), __float_as_uint(b1[2*tid+1]));
        sb1[tid] = p;
    }
    for (int i = tid; i < 5*20*70; i += 256) {
        int c  = i / 1400;
        int r  = i % 1400;
        int yy = r / 70;
        int xx = r % 70;
        int gy = y0 + yy - 2;
        int gx = x0 + xx - 2;
        float v = 0.0f;
        if (gy >= 0 && gy < NXX && gx >= 0 && gx < NYY)
            v = in[(size_t)(b*TT + c)*PLANE + gy*NYY + gx];
        sin_f[i] = v;
    }
    float bias2[5];
    #pragma unroll
    for (int o = 0; o < 5; o++) bias2[o] = b2[o];

    __syncthreads();

    // ---- fused cost row (cost of the INPUT field over this tile) ----
    if (cost_row >= 0) {
        float s_mse = 0.0f, s_oi = 0.0f;
        #pragma unroll 1
        for (int e = tid; e < 5*16*64; e += 256) {      // 20 iters
            int c  = e >> 10;
            int r  = e & 1023;
            int oy = r >> 6;
            int ox = r & 63;
            const float* sp = &sin_f[(c*20 + oy + 2)*70 + ox + 2];
            float xv = sp[0];
            float xr = sp[1];
            float xd = sp[70];
            float xt = (c < TT-1) ? sp[1400] : 0.0f;

            int gi = b*NPB + c*PLANE + (y0 + oy)*NYY + x0 + ox;
            float gv = gt[gi];
            float yv = yobs[gi];
            float mv = (float)mask[gi];

            float gg = gv - xv;
            s_mse += gg*gg;
            float d  = xv - yv;
            float nb = xr + xd + xt;
            s_oi += 1000.0f*mv*d*d + 6.01f*xv*xv - 2.0f*xv*nb;
        }
        double dm = (double)s_mse, doi = (double)s_oi;
        #pragma unroll
        for (int off = 16; off; off >>= 1) {
            dm  += __shfl_down_sync(0xffffffffu, dm,  off);
            doi += __shfl_down_sync(0xffffffffu, doi, off);
        }
        int lane = tid & 31, w = tid >> 5;
        if (lane == 0) { red[0][w] = dm; red[1][w] = doi; }
        __syncthreads();
        if (tid == 0) {
            double a = 0.0, c2 = 0.0;
            #pragma unroll
            for (int i2 = 0; i2 < 8; i2++) { a += red[0][i2]; c2 += red[1][i2]; }
            atomicAdd(&g_acc[b][cost_row][0], a);
            atomicAdd(&g_acc[b][cost_row][1], c2);
        }
    }

    // conv2 output accumulators: 2 windows x 2 x-adjacent px, 5 oc
    ull acc2[4][5];
    #pragma unroll
    for (int p = 0; p < 4; p++)
        #pragma unroll
        for (int o = 0; o < 5; o++) acc2[p][o] = 0ull;

    int i2 = tid & 15;           // window base px = 2*i2 and 2*i2+32
    int oy = tid >> 4;           // 0..15

    #pragma unroll 1
    for (int ch = 0; ch < 8; ch++) {     // 8 chunks of 8 hidden channels
        __syncthreads();                  // shid free (prev phase-B done)

        // ---- phase A: conv1 -> relu -> shid (8 ch = 4 cpairs) ----
        #pragma unroll 1
        for (int u = tid; u < 396; u += 256) {
            int hy  = u / 22;             // 0..17
            int g   = u - hy*22;
            int hx0 = 3*g;                // 0..63 (covers hx 0..65)

            ull a1[3][4];
            #pragma unroll
            for (int q = 0; q < 4; q++) {
                ull bv = sb1[ch*4 + q];
                a1[0][q] = bv; a1[1][q] = bv; a1[2][q] = bv;
            }

            #pragma unroll 1
            for (int c = 0; c < TT; c++) {
                #pragma unroll
                for (int ky = 0; ky < 3; ky++) {
                    const float* row = &sin_f[(c*20 + hy + ky)*70 + hx0];
                    ull vv[5];
                    #pragma unroll
                    for (int t = 0; t < 5; t++) {
                        unsigned int bits = __float_as_uint(row[t]);
                        PACK2(vv[t], bits, bits);
                    }
                    #pragma unroll
                    for (int kx = 0; kx < 3; kx++) {
                        const ulonglong2* wq =
                            (const ulonglong2*)&sw1[(c*9 + ky*3 + kx)*32 + ch*4];
                        ulonglong2 w01 = wq[0];
                        ulonglong2 w23 = wq[1];
                        #pragma unroll
                        for (int px = 0; px < 3; px++) {
                            ull v = vv[kx + px];
                            FMA2(a1[px][0], w01.x, v, a1[px][0]);
                            FMA2(a1[px][1], w01.y, v, a1[px][1]);
                            FMA2(a1[px][2], w23.x, v, a1[px][2]);
                            FMA2(a1[px][3], w23.y, v, a1[px][3]);
                        }
                    }
                }
            }

            // store: relu; zero outside image (conv2 must see zero pad)
            int gyh = y0 + hy - 1;
            bool yok = (gyh >= 0) && (gyh < NXX);
            #pragma unroll
            for (int px = 0; px < 3; px++) {
                int hx  = hx0 + px;
                int gxh = x0 + hx - 1;
                bool ok = yok && (gxh >= 0) && (gxh < NYY);
                #pragma unroll
                for (int q = 0; q < 4; q++) {
                    unsigned int lo, hi;
                    UNPACK2(lo, hi, a1[px][q]);
                    float fl = fmaxf(__uint_as_float(lo), 0.0f);
                    float fh = fmaxf(__uint_as_float(hi), 0.0f);
                    if (!ok) { fl = 0.0f; fh = 0.0f; }
                    ull pv;
                    PACK2(pv, __float_as_uint(fl), __float_as_uint(fh));
                    shid[(q*18 + hy)*68 + hx] = pv;
                }
            }
        }
        __syncthreads();

        // ---- phase B: conv2 accumulate, 2 windows share hoisted weights ----
        #pragma unroll 1
        for (int cp = 0; cp < 4; cp++) {
            int cpg = ch*4 + cp;
            #pragma unroll
            for (int ky = 0; ky < 3; ky++) {
                const ull* wt = &sw2[(cpg*9 + ky*3)*6];
                ulonglong2 w0a = *(const ulonglong2*)&wt[0];
                ulonglong2 w0b = *(const ulonglong2*)&wt[2];
                ull        w0c = wt[4];
                ulonglong2 w1a = *(const ulonglong2*)&wt[6];
                ulonglong2 w1b = *(const ulonglong2*)&wt[8];
                ull        w1c = wt[10];
                ulonglong2 w2a = *(const ulonglong2*)&wt[12];
                ulonglong2 w2b = *(const ulonglong2*)&wt[14];
                ull        w2c = wt[16];

                const ull* rv = &shid[(cp*18 + oy + ky)*68 + 2*i2];
                #pragma unroll
                for (int wd = 0; wd < 2; wd++) {
                    const ull* rw = rv + wd*32;
                    ulonglong2 vA = *(const ulonglong2*)&rw[0];
                    ulonglong2 vB = *(const ulonglong2*)&rw[2];
                    ull v0 = vA.x, v1 = vA.y, v2 = vB.x, v3 = vB.y;
                    ull* a0 = acc2[wd*2 + 0];
                    ull* a1p = acc2[wd*2 + 1];

                    FMA2(a0[0], w0a.x, v0, a0[0]);
                    FMA2(a0[1], w0a.y, v0, a0[1]);
                    FMA2(a0[2], w0b.x, v0, a0[2]);
                    FMA2(a0[3], w0b.y, v0, a0[3]);
                    FMA2(a0[4], w0c,   v0, a0[4]);
                    FMA2(a0[0], w1a.x, v1, a0[0]);
                    FMA2(a0[1], w1a.y, v1, a0[1]);
                    FMA2(a0[2], w1b.x, v1, a0[2]);
                    FMA2(a0[3], w1b.y, v1, a0[3]);
                    FMA2(a0[4], w1c,   v1, a0[4]);
                    FMA2(a0[0], w2a.x, v2, a0[0]);
                    FMA2(a0[1], w2a.y, v2, a0[1]);
                    FMA2(a0[2], w2b.x, v2, a0[2]);
                    FMA2(a0[3], w2b.y, v2, a0[3]);
                    FMA2(a0[4], w2c,   v2, a0[4]);

                    FMA2(a1p[0], w0a.x, v1, a1p[0]);
                    FMA2(a1p[1], w0a.y, v1, a1p[1]);
                    FMA2(a1p[2], w0b.x, v1, a1p[2]);
                    FMA2(a1p[3], w0b.y, v1, a1p[3]);
                    FMA2(a1p[4], w0c,   v1, a1p[4]);
                    FMA2(a1p[0], w1a.x, v2, a1p[0]);
                    FMA2(a1p[1], w1a.y, v2, a1p[1]);
                    FMA2(a1p[2], w1b.x, v2, a1p[2]);
                    FMA2(a1p[3], w1b.y, v2, a1p[3]);
                    FMA2(a1p[4], w1c,   v2, a1p[4]);
                    FMA2(a1p[0], w2a.x, v3, a1p[0]);
                    FMA2(a1p[1], w2a.y, v3, a1p[1]);
                    FMA2(a1p[2], w2b.x, v3, a1p[2]);
                    FMA2(a1p[3], w2b.y, v3, a1p[3]);
                    FMA2(a1p[4], w2c,   v3, a1p[4]);
                }
            }
        }
    }

    // ---- epilogue: sum halves + bias, optional mask blend, write 2x2 px ----
    int oyg = y0 + oy;
    #pragma unroll
    for (int wd = 0; wd < 2; wd++) {
        int oxg  = x0 + 2*i2 + wd*32;
        int base = b*NPB + oyg*NYY + oxg;
        #pragma unroll
        for (int o = 0; o < 5; o++) {
            unsigned int lo, hi;
            UNPACK2(lo, hi, acc2[wd*2 + 0][o]);
            float r0 = __uint_as_float(lo) + __uint_as_float(hi) + bias2[o];
            UNPACK2(lo, hi, acc2[wd*2 + 1][o]);
            float r1 = __uint_as_float(lo) + __uint_as_float(hi) + bias2[o];
            int idx = base + o*PLANE;
            if (apply_mask) {
                int2   m2 = *(const int2*)&mask[idx];
                float2 y2 = *(const float2*)&yobs[idx];
                float m0 = (float)m2.x, m1 = (float)m2.y;
                r0 = r0*(1.0f - m0) + y2.x*m0;
                r1 = r1*(1.0f - m1) + y2.y*m1;
            }
            *(float2*)&out[idx] = make_float2(r0, r1);
        }
    }
}

// ---------------- finalize cmp_loss [B, NFP+1, 2] ----------------------------
__global__ void finalize_kernel(float* __restrict__ cmp)
{
    int i = threadIdx.x;
    if (i < BB*(NFP+1)*2) {
        int b = i / ((NFP+1)*2);
        int r = (i / 2) % (NFP+1);
        int c = i & 1;
        double v = g_acc[b][r][c];
        if (c == 0) v /= (double)NPB;       // mean for MSE
        cmp[i] = (float)v;
    }
}

// ---------------- launcher ---------------------------------------------------
extern "C" void kernel_launch(void* const* d_in, const int* in_sizes, int n_in,
                              void* d_out, int out_size)
{
    const float* gt   = (const float*)d_in[0];
    const float* x    = (const float*)d_in[1];
    const float* yobs = (const float*)d_in[2];
    const int*   mask = (const int*)  d_in[3];
    const float* W1   = (const float*)d_in[4];
    const float* b1   = (const float*)d_in[5];
    const float* W2   = (const float*)d_in[6];
    const float* b2   = (const float*)d_in[7];
    (void)in_sizes; (void)n_in;

    float* out     = (float*)d_out;
    float* out_x   = out;                                  // [B,5,512,512]
    float* out_cmp = out + (out_size - BB*(NFP+1)*2);      // [B,NFP+1,2]

    void *p0, *p2;
    cudaGetSymbolAddress(&p0, g_xbuf);
    cudaGetSymbolAddress(&p2, g_acc);
    float* xb0 = (float*)p0;
    float* xb1 = xb0 + FIELD;

    cudaFuncSetAttribute(fused_phi_kernel,
                         cudaFuncAttributeMaxDynamicSharedMemorySize, FS_BYTES);

    cudaMemsetAsync(p2, 0, sizeof(double)*BB*(NFP+1)*2);            // launch #0
    cudaMemcpyAsync(xb0, x, sizeof(float)*FIELD, cudaMemcpyDeviceToDevice); // #1

    dim3 cgrid(CGRP/256, BB);         // (640, 4)
    dim3 gf(NYY/64, NXX/16, BB);      // (8, 32, 4)

    float* cur = xb0;
    float* nxt = xb1;
    for (int k = 0; k < NFP; k++) {                                  // #2..#5
        fused_phi_kernel<<<gf, 256, FS_BYTES>>>(cur, W1, b1, W2, b2,
                                                gt, yobs, mask, nxt, 1, k);
        float* tmp = cur; cur = nxt; nxt = tmp;
    }
    // final phi (no mask blend, no fused cost), straight into d_out
    fused_phi_kernel<<<gf, 256, FS_BYTES>>>(cur, W1, b1, W2, b2,
                                            gt, yobs, mask, out_x, 0, -1);
    cost_kernel<<<cgrid, 256>>>(out_x, gt, yobs, mask, NFP);
    finalize_kernel<<<1, 64>>>(out_cmp);
}